// round 1
// baseline (speedup 1.0000x reference)
#include <cuda_runtime.h>
#include <math.h>

#define D_MODEL 1024
#define NHEAD   16
#define HEAD_DIM 64
#define D_FF    4096
#define BATCH   2
#define SEQ     2048
#define MROWS   (BATCH * SEQ)   // 4096
#define LN_EPS  1e-5f

// ---------------------------------------------------------------------------
// Scratch (device globals: allocation-free per harness rules)
// ---------------------------------------------------------------------------
__device__ float g_nx  [MROWS * D_MODEL];   // ln1(x)
__device__ float g_q   [MROWS * D_MODEL];   // [B*H, L, 64]
__device__ float g_k   [MROWS * D_MODEL];   // [B*H, L, 64]
__device__ float g_v   [MROWS * D_MODEL];   // [B*H, L, 64]
__device__ float g_attn[MROWS * D_MODEL];   // [B, L, D]
__device__ float g_x1  [MROWS * D_MODEL];   // x + attn@Wo + bo
__device__ float g_nx2 [MROWS * D_MODEL];   // ln2(x1)
__device__ float g_ffh [MROWS * D_FF];      // gelu(nx2@W1 + bf1)

// ---------------------------------------------------------------------------
// LayerNorm: one block per row, 256 threads, float4
// ---------------------------------------------------------------------------
__global__ void ln_kernel(const float* __restrict__ x, const float* __restrict__ g,
                          const float* __restrict__ b, float* __restrict__ out)
{
    int row = blockIdx.x;
    int tid = threadIdx.x;
    const float* xr = x + (size_t)row * D_MODEL;
    int c = tid * 4;
    float4 v = *(const float4*)(xr + c);

    float s  = v.x + v.y + v.z + v.w;
    float ss = v.x*v.x + v.y*v.y + v.z*v.z + v.w*v.w;
    #pragma unroll
    for (int o = 16; o > 0; o >>= 1) {
        s  += __shfl_xor_sync(0xffffffffu, s,  o);
        ss += __shfl_xor_sync(0xffffffffu, ss, o);
    }
    __shared__ float smS[8], smSS[8];
    int w = tid >> 5, lane = tid & 31;
    if (lane == 0) { smS[w] = s; smSS[w] = ss; }
    __syncthreads();
    float tot = 0.f, tot2 = 0.f;
    #pragma unroll
    for (int i = 0; i < 8; i++) { tot += smS[i]; tot2 += smSS[i]; }

    float mu   = tot  * (1.0f / D_MODEL);
    float var  = tot2 * (1.0f / D_MODEL) - mu * mu;
    float rstd = rsqrtf(var + LN_EPS);

    float4 gv = *(const float4*)(g + c);
    float4 bv = *(const float4*)(b + c);
    float4 o;
    o.x = (v.x - mu) * rstd * gv.x + bv.x;
    o.y = (v.y - mu) * rstd * gv.y + bv.y;
    o.z = (v.z - mu) * rstd * gv.z + bv.z;
    o.w = (v.w - mu) * rstd * gv.w + bv.w;
    *(float4*)(out + (size_t)row * D_MODEL + c) = o;
}

// ---------------------------------------------------------------------------
// SIMT fp32 GEMM: C[M,N] = A[M,K] @ W[K,N] (+ bias) (+ epilogue)
// BM=BN=128, BK=16, 256 threads, 8x8 microtile, register prefetch.
// MODE 0: QKV  -> write head-permuted layout [B*H, L, 64]
// MODE 1: GELU -> C = gelu(acc + bias)
// MODE 2: RES  -> C = res + acc + bias
// ---------------------------------------------------------------------------
__device__ __forceinline__ float gelu_exact(float v) {
    return 0.5f * v * (1.0f + erff(v * 0.70710678118654752f));
}

#define BM 128
#define BN 128
#define BK 16

template<int MODE>
__global__ __launch_bounds__(256, 2)
void gemm_kernel(const float* __restrict__ A, const float* __restrict__ Bw,
                 const float* __restrict__ bias, const float* __restrict__ res,
                 float* __restrict__ C, int M, int N, int K)
{
    __shared__ float As[BK][BM];
    __shared__ float Bs[BK][BN + 4];

    int tid = threadIdx.x;
    int bx = blockIdx.x, by = blockIdx.y;
    int tx = tid & 15, ty = tid >> 4;

    // A loader: row am = tid>>1, k-offset ak = (tid&1)*8  (8 consecutive floats)
    int am = tid >> 1;
    int ak = (tid & 1) * 8;
    const float* Aptr = A + (size_t)(by * BM + am) * K + ak;
    // B loader: row bk = tid>>4, n-offset bn = (tid&15)*8
    int bkr = tid >> 4;
    int bn  = (tid & 15) * 8;
    const float* Bptr = Bw + (size_t)bkr * N + (size_t)bx * BN + bn;

    float4 a0 = *(const float4*)(Aptr);
    float4 a1 = *(const float4*)(Aptr + 4);
    float4 b0 = *(const float4*)(Bptr);
    float4 b1 = *(const float4*)(Bptr + 4);

    float acc[8][8];
    #pragma unroll
    for (int i = 0; i < 8; i++)
        #pragma unroll
        for (int j = 0; j < 8; j++) acc[i][j] = 0.f;

    int nk = K / BK;
    for (int kt = 0; kt < nk; kt++) {
        // commit prefetched tile to smem
        As[ak+0][am] = a0.x; As[ak+1][am] = a0.y; As[ak+2][am] = a0.z; As[ak+3][am] = a0.w;
        As[ak+4][am] = a1.x; As[ak+5][am] = a1.y; As[ak+6][am] = a1.z; As[ak+7][am] = a1.w;
        *(float4*)&Bs[bkr][bn]     = b0;
        *(float4*)&Bs[bkr][bn + 4] = b1;
        __syncthreads();

        if (kt + 1 < nk) {
            a0 = *(const float4*)(Aptr + (kt + 1) * BK);
            a1 = *(const float4*)(Aptr + (kt + 1) * BK + 4);
            b0 = *(const float4*)(Bptr + (size_t)(kt + 1) * BK * N);
            b1 = *(const float4*)(Bptr + (size_t)(kt + 1) * BK * N + 4);
        }

        #pragma unroll
        for (int k = 0; k < BK; k++) {
            float af[8], bf[8];
            *(float4*)&af[0] = *(const float4*)&As[k][ty * 8];
            *(float4*)&af[4] = *(const float4*)&As[k][ty * 8 + 4];
            *(float4*)&bf[0] = *(const float4*)&Bs[k][tx * 8];
            *(float4*)&bf[4] = *(const float4*)&Bs[k][tx * 8 + 4];
            #pragma unroll
            for (int i = 0; i < 8; i++)
                #pragma unroll
                for (int j = 0; j < 8; j++)
                    acc[i][j] = fmaf(af[i], bf[j], acc[i][j]);
        }
        __syncthreads();
    }

    int row0 = by * BM + ty * 8;
    int col0 = bx * BN + tx * 8;
    #pragma unroll
    for (int i = 0; i < 8; i++) {
        int row = row0 + i;
        #pragma unroll
        for (int j = 0; j < 8; j++) {
            int col = col0 + j;
            float v = acc[i][j] + bias[col];
            if (MODE == 1) v = gelu_exact(v);
            if (MODE == 2) v += res[(size_t)row * N + col];
            if (MODE == 0) {
                // row = b*SEQ + l, col = h*64 + d  ->  [(b*H+h)*SEQ + l]*64 + d
                int b = row >> 11, l = row & (SEQ - 1);
                int h = col >> 6,  d = col & 63;
                C[(((size_t)(b * NHEAD + h) * SEQ) + l) * HEAD_DIM + d] = v;
            } else {
                C[(size_t)row * N + col] = v;
            }
        }
    }
}

// ---------------------------------------------------------------------------
// Flash-style causal attention.
// Q,K,V: [B*H, L, 64]. Grid: (qtile=L/64, B*H). 256 threads.
// Each block: 64 queries, iterates lower-triangular key tiles of 64.
// Thread (ty,tx) owns a 4x4 tile of S (rows q=ty*4+i, cols k=tx*4+j)
// and a 4x4 tile of O (rows q=ty*4+i, cols d=tx*4+j).
// ---------------------------------------------------------------------------
#define ATTN_PAD 65
#define ATTN_SMEM (4 * 64 * ATTN_PAD * (int)sizeof(float))

__global__ __launch_bounds__(256)
void attn_kernel(const float* __restrict__ Q, const float* __restrict__ K,
                 const float* __restrict__ V, float* __restrict__ out)
{
    extern __shared__ float sm[];
    float (*Qs)[ATTN_PAD] = (float(*)[ATTN_PAD])(sm);
    float (*Ks)[ATTN_PAD] = (float(*)[ATTN_PAD])(sm + 64 * ATTN_PAD);
    float (*Vs)[ATTN_PAD] = (float(*)[ATTN_PAD])(sm + 2 * 64 * ATTN_PAD);
    float (*Ps)[ATTN_PAD] = (float(*)[ATTN_PAD])(sm + 3 * 64 * ATTN_PAD);

    int qt  = blockIdx.x;
    int bh  = blockIdx.y;
    int tid = threadIdx.x;
    int tx = tid & 15, ty = tid >> 4;

    const float* Qb = Q + (size_t)bh * SEQ * HEAD_DIM;
    const float* Kb = K + (size_t)bh * SEQ * HEAD_DIM;
    const float* Vb = V + (size_t)bh * SEQ * HEAD_DIM;

    // load Q tile (64x64)
    #pragma unroll
    for (int i = 0; i < 16; i++) {
        int e = tid + i * 256;
        int r = e >> 6, c = e & 63;
        Qs[r][c] = Qb[(size_t)(qt * 64 + r) * HEAD_DIM + c];
    }

    float acc[4][4];
    float m_i[4], l_i[4];
    #pragma unroll
    for (int i = 0; i < 4; i++) {
        m_i[i] = -1e30f; l_i[i] = 0.f;
        #pragma unroll
        for (int j = 0; j < 4; j++) acc[i][j] = 0.f;
    }
    const float scale = 0.125f;  // 1/sqrt(64)

    for (int kt = 0; kt <= qt; kt++) {
        __syncthreads();  // prior PV reads of Ps/Vs complete
        #pragma unroll
        for (int i = 0; i < 16; i++) {
            int e = tid + i * 256;
            int r = e >> 6, c = e & 63;
            Ks[r][c] = Kb[(size_t)(kt * 64 + r) * HEAD_DIM + c];
            Vs[r][c] = Vb[(size_t)(kt * 64 + r) * HEAD_DIM + c];
        }
        __syncthreads();

        // S = (Q K^T)
        float s[4][4];
        #pragma unroll
        for (int i = 0; i < 4; i++)
            #pragma unroll
            for (int j = 0; j < 4; j++) s[i][j] = 0.f;

        for (int d = 0; d < 64; d++) {
            float a0 = Qs[ty*4+0][d], a1 = Qs[ty*4+1][d];
            float a2 = Qs[ty*4+2][d], a3 = Qs[ty*4+3][d];
            float q0 = Ks[tx*4+0][d], q1 = Ks[tx*4+1][d];
            float q2 = Ks[tx*4+2][d], q3 = Ks[tx*4+3][d];
            s[0][0] = fmaf(a0,q0,s[0][0]); s[0][1] = fmaf(a0,q1,s[0][1]);
            s[0][2] = fmaf(a0,q2,s[0][2]); s[0][3] = fmaf(a0,q3,s[0][3]);
            s[1][0] = fmaf(a1,q0,s[1][0]); s[1][1] = fmaf(a1,q1,s[1][1]);
            s[1][2] = fmaf(a1,q2,s[1][2]); s[1][3] = fmaf(a1,q3,s[1][3]);
            s[2][0] = fmaf(a2,q0,s[2][0]); s[2][1] = fmaf(a2,q1,s[2][1]);
            s[2][2] = fmaf(a2,q2,s[2][2]); s[2][3] = fmaf(a2,q3,s[2][3]);
            s[3][0] = fmaf(a3,q0,s[3][0]); s[3][1] = fmaf(a3,q1,s[3][1]);
            s[3][2] = fmaf(a3,q2,s[3][2]); s[3][3] = fmaf(a3,q3,s[3][3]);
        }

        // scale + causal mask (diagonal tile only)
        if (kt == qt) {
            #pragma unroll
            for (int i = 0; i < 4; i++)
                #pragma unroll
                for (int j = 0; j < 4; j++) {
                    int qg = ty * 4 + i, kg = tx * 4 + j;
                    s[i][j] = (kg > qg) ? -1e30f : s[i][j] * scale;
                }
        } else {
            #pragma unroll
            for (int i = 0; i < 4; i++)
                #pragma unroll
                for (int j = 0; j < 4; j++) s[i][j] *= scale;
        }

        // online softmax per row (16-thread group shares a row set)
        #pragma unroll
        for (int i = 0; i < 4; i++) {
            float mx = fmaxf(fmaxf(s[i][0], s[i][1]), fmaxf(s[i][2], s[i][3]));
            #pragma unroll
            for (int o = 8; o > 0; o >>= 1)
                mx = fmaxf(mx, __shfl_xor_sync(0xffffffffu, mx, o));
            float mnew = fmaxf(m_i[i], mx);
            float corr = __expf(m_i[i] - mnew);
            float rsum = 0.f;
            #pragma unroll
            for (int j = 0; j < 4; j++) {
                float p = __expf(s[i][j] - mnew);
                s[i][j] = p;
                rsum += p;
            }
            #pragma unroll
            for (int o = 8; o > 0; o >>= 1)
                rsum += __shfl_xor_sync(0xffffffffu, rsum, o);
            l_i[i] = l_i[i] * corr + rsum;
            m_i[i] = mnew;
            #pragma unroll
            for (int j = 0; j < 4; j++) {
                acc[i][j] *= corr;
                Ps[ty*4+i][tx*4+j] = s[i][j];
            }
        }
        __syncthreads();

        // O += P @ V   (thread's O cols are d = tx*4+j)
        for (int k = 0; k < 64; k++) {
            float p0 = Ps[ty*4+0][k], p1 = Ps[ty*4+1][k];
            float p2 = Ps[ty*4+2][k], p3 = Ps[ty*4+3][k];
            float v0 = Vs[k][tx*4+0], v1 = Vs[k][tx*4+1];
            float v2 = Vs[k][tx*4+2], v3 = Vs[k][tx*4+3];
            acc[0][0] = fmaf(p0,v0,acc[0][0]); acc[0][1] = fmaf(p0,v1,acc[0][1]);
            acc[0][2] = fmaf(p0,v2,acc[0][2]); acc[0][3] = fmaf(p0,v3,acc[0][3]);
            acc[1][0] = fmaf(p1,v0,acc[1][0]); acc[1][1] = fmaf(p1,v1,acc[1][1]);
            acc[1][2] = fmaf(p1,v2,acc[1][2]); acc[1][3] = fmaf(p1,v3,acc[1][3]);
            acc[2][0] = fmaf(p2,v0,acc[2][0]); acc[2][1] = fmaf(p2,v1,acc[2][1]);
            acc[2][2] = fmaf(p2,v2,acc[2][2]); acc[2][3] = fmaf(p2,v3,acc[2][3]);
            acc[3][0] = fmaf(p3,v0,acc[3][0]); acc[3][1] = fmaf(p3,v1,acc[3][1]);
            acc[3][2] = fmaf(p3,v2,acc[3][2]); acc[3][3] = fmaf(p3,v3,acc[3][3]);
        }
    }

    // write attn_out in [B, L, D] layout
    int b = bh >> 4, h = bh & 15;
    #pragma unroll
    for (int i = 0; i < 4; i++) {
        float inv_l = 1.0f / l_i[i];
        int l = qt * 64 + ty * 4 + i;
        #pragma unroll
        for (int j = 0; j < 4; j++) {
            int d = tx * 4 + j;
            out[((size_t)(b * SEQ + l)) * D_MODEL + h * HEAD_DIM + d] = acc[i][j] * inv_l;
        }
    }
}

// ---------------------------------------------------------------------------
// Launch
// ---------------------------------------------------------------------------
extern "C" void kernel_launch(void* const* d_in, const int* in_sizes, int n_in,
                              void* d_out, int out_size)
{
    const float* x   = (const float*)d_in[0];
    // d_in[1] = mask (int32) — causal by construction; not needed
    const float* Wq  = (const float*)d_in[2];
    const float* bq  = (const float*)d_in[3];
    const float* Wk  = (const float*)d_in[4];
    const float* bk  = (const float*)d_in[5];
    const float* Wv  = (const float*)d_in[6];
    const float* bv  = (const float*)d_in[7];
    const float* Wo  = (const float*)d_in[8];
    const float* bo  = (const float*)d_in[9];
    const float* g1  = (const float*)d_in[10];
    const float* b1  = (const float*)d_in[11];
    const float* g2  = (const float*)d_in[12];
    const float* b2  = (const float*)d_in[13];
    const float* W1  = (const float*)d_in[14];
    const float* bf1 = (const float*)d_in[15];
    const float* W2  = (const float*)d_in[16];
    const float* bf2 = (const float*)d_in[17];
    float* out = (float*)d_out;

    float *p_nx, *p_q, *p_k, *p_v, *p_attn, *p_x1, *p_nx2, *p_ffh;
    cudaGetSymbolAddress((void**)&p_nx,   g_nx);
    cudaGetSymbolAddress((void**)&p_q,    g_q);
    cudaGetSymbolAddress((void**)&p_k,    g_k);
    cudaGetSymbolAddress((void**)&p_v,    g_v);
    cudaGetSymbolAddress((void**)&p_attn, g_attn);
    cudaGetSymbolAddress((void**)&p_x1,   g_x1);
    cudaGetSymbolAddress((void**)&p_nx2,  g_nx2);
    cudaGetSymbolAddress((void**)&p_ffh,  g_ffh);

    cudaFuncSetAttribute(attn_kernel, cudaFuncAttributeMaxDynamicSharedMemorySize, ATTN_SMEM);

    dim3 t256(256);

    // 1. nx = LN1(x)
    ln_kernel<<<MROWS, t256>>>(x, g1, b1, p_nx);

    // 2. Q/K/V = nx @ W + b (head-permuted output)
    dim3 gQKV(D_MODEL / BN, MROWS / BM);
    gemm_kernel<0><<<gQKV, t256>>>(p_nx, Wq, bq, nullptr, p_q, MROWS, D_MODEL, D_MODEL);
    gemm_kernel<0><<<gQKV, t256>>>(p_nx, Wk, bk, nullptr, p_k, MROWS, D_MODEL, D_MODEL);
    gemm_kernel<0><<<gQKV, t256>>>(p_nx, Wv, bv, nullptr, p_v, MROWS, D_MODEL, D_MODEL);

    // 3. causal flash attention
    dim3 gAttn(SEQ / 64, BATCH * NHEAD);
    attn_kernel<<<gAttn, t256, ATTN_SMEM>>>(p_q, p_k, p_v, p_attn);

    // 4. x1 = x + attn @ Wo + bo
    gemm_kernel<2><<<gQKV, t256>>>(p_attn, Wo, bo, x, p_x1, MROWS, D_MODEL, D_MODEL);

    // 5. nx2 = LN2(x1)
    ln_kernel<<<MROWS, t256>>>(p_x1, g2, b2, p_nx2);

    // 6. h = gelu(nx2 @ W1 + bf1)
    dim3 gF1(D_FF / BN, MROWS / BM);
    gemm_kernel<1><<<gF1, t256>>>(p_nx2, W1, bf1, nullptr, p_ffh, MROWS, D_FF, D_MODEL);

    // 7. out = x1 + h @ W2 + bf2
    gemm_kernel<2><<<gQKV, t256>>>(p_ffh, W2, bf2, p_x1, out, MROWS, D_MODEL, D_FF);
}

// round 3
// speedup vs baseline: 1.9723x; 1.9723x over previous
#include <cuda_runtime.h>
#include <math.h>
#include <stdint.h>

#define D_MODEL 1024
#define NHEAD   16
#define HEAD_DIM 64
#define D_FF    4096
#define BATCH   2
#define SEQ     2048
#define MROWS   (BATCH * SEQ)   // 4096
#define LN_EPS  1e-5f

// ---------------------------------------------------------------------------
// Scratch (device globals)
// ---------------------------------------------------------------------------
__device__ float g_nx  [MROWS * D_MODEL];
__device__ float g_q   [MROWS * D_MODEL];
__device__ float g_k   [MROWS * D_MODEL];
__device__ float g_v   [MROWS * D_MODEL];
__device__ float g_attn[MROWS * D_MODEL];
__device__ float g_x1  [MROWS * D_MODEL];
__device__ float g_nx2 [MROWS * D_MODEL];
__device__ float g_ffh [MROWS * D_FF];
__device__ float g_wqt [D_MODEL * D_MODEL];
__device__ float g_wkt [D_MODEL * D_MODEL];
__device__ float g_wvt [D_MODEL * D_MODEL];
__device__ float g_wot [D_MODEL * D_MODEL];
__device__ float g_w1t [D_MODEL * D_FF];
__device__ float g_w2t [D_MODEL * D_FF];

// ---------------------------------------------------------------------------
// Helpers
// ---------------------------------------------------------------------------
__device__ __forceinline__ uint32_t smem_u32(const void* p) {
    uint32_t a;
    asm("{ .reg .u64 t; cvta.to.shared.u64 t, %1; cvt.u32.u64 %0, t; }" : "=r"(a) : "l"(p));
    return a;
}
__device__ __forceinline__ float tf32r(float f) {
    uint32_t u;
    asm("cvt.rna.tf32.f32 %0, %1;" : "=r"(u) : "f"(f));
    return __uint_as_float(u);
}
__device__ __forceinline__ float gelu_exact(float v) {
    return 0.5f * v * (1.0f + erff(v * 0.70710678118654752f));
}

#define CP_ASYNC(dst, src) \
    asm volatile("cp.async.cg.shared.global [%0], [%1], 16;" :: "r"(dst), "l"(src))
#define CP_COMMIT() asm volatile("cp.async.commit_group;")
#define CP_WAIT1()  asm volatile("cp.async.wait_group 1;")
#define CP_WAIT0()  asm volatile("cp.async.wait_group 0;")

__device__ __forceinline__ void mma_tf32(float* c,
    uint32_t a0, uint32_t a1, uint32_t a2, uint32_t a3, uint32_t b0, uint32_t b1)
{
    asm volatile(
        "mma.sync.aligned.m16n8k8.row.col.f32.tf32.tf32.f32 "
        "{%0,%1,%2,%3}, {%4,%5,%6,%7}, {%8,%9}, {%0,%1,%2,%3};"
        : "+f"(c[0]), "+f"(c[1]), "+f"(c[2]), "+f"(c[3])
        : "r"(a0), "r"(a1), "r"(a2), "r"(a3), "r"(b0), "r"(b1));
}

// ---------------------------------------------------------------------------
// Weight transpose (+ tf32 rounding): in[K,N] -> out[N,K]
// ---------------------------------------------------------------------------
__global__ void transpose_kernel(const float* __restrict__ in, float* __restrict__ out,
                                 int K, int N)
{
    __shared__ float tile[32][33];
    int x = blockIdx.x * 32 + threadIdx.x;
    int y0 = blockIdx.y * 32;
    #pragma unroll
    for (int i = threadIdx.y; i < 32; i += 8)
        tile[i][threadIdx.x] = in[(size_t)(y0 + i) * N + x];
    __syncthreads();
    int xo = blockIdx.y * 32 + threadIdx.x;
    int yo0 = blockIdx.x * 32;
    #pragma unroll
    for (int i = threadIdx.y; i < 32; i += 8)
        out[(size_t)(yo0 + i) * K + xo] = tf32r(tile[threadIdx.x][i]);
}

// ---------------------------------------------------------------------------
// LayerNorm (output tf32-rounded: feeds GEMM A operands)
// ---------------------------------------------------------------------------
__global__ void ln_kernel(const float* __restrict__ x, const float* __restrict__ g,
                          const float* __restrict__ b, float* __restrict__ out)
{
    int row = blockIdx.x;
    int tid = threadIdx.x;
    const float* xr = x + (size_t)row * D_MODEL;
    int c = tid * 4;
    float4 v = *(const float4*)(xr + c);

    float s  = v.x + v.y + v.z + v.w;
    float ss = v.x*v.x + v.y*v.y + v.z*v.z + v.w*v.w;
    #pragma unroll
    for (int o = 16; o > 0; o >>= 1) {
        s  += __shfl_xor_sync(0xffffffffu, s,  o);
        ss += __shfl_xor_sync(0xffffffffu, ss, o);
    }
    __shared__ float smS[8], smSS[8];
    int w = tid >> 5, lane = tid & 31;
    if (lane == 0) { smS[w] = s; smSS[w] = ss; }
    __syncthreads();
    float tot = 0.f, tot2 = 0.f;
    #pragma unroll
    for (int i = 0; i < 8; i++) { tot += smS[i]; tot2 += smSS[i]; }

    float mu   = tot  * (1.0f / D_MODEL);
    float var  = tot2 * (1.0f / D_MODEL) - mu * mu;
    float rstd = rsqrtf(var + LN_EPS);

    float4 gv = *(const float4*)(g + c);
    float4 bv = *(const float4*)(b + c);
    float4 o;
    o.x = tf32r((v.x - mu) * rstd * gv.x + bv.x);
    o.y = tf32r((v.y - mu) * rstd * gv.y + bv.y);
    o.z = tf32r((v.z - mu) * rstd * gv.z + bv.z);
    o.w = tf32r((v.w - mu) * rstd * gv.w + bv.w);
    *(float4*)(out + (size_t)row * D_MODEL + c) = o;
}

// ---------------------------------------------------------------------------
// tf32 mma.sync GEMM: C[M,N] = A[M,K] @ WT[N,K]^T
// BM=128, BN=128, BK=32, 256 thr (8 warps, 2x4), warp tile 64x32 (4x4 m16n8k8).
// cp.async double-buffered SMEM [128][36] (conflict-free fragment loads).
// ---------------------------------------------------------------------------
#define BM 128
#define BN 128
#define BKg 32
#define LDAs 36                    // BK + 4 pad
#define ASZ (BM * LDAs)            // floats per A stage
#define STAGEF (2 * ASZ)           // A + B per stage
#define GEMM_SMEM (2 * STAGEF * 4) // 73728 bytes

struct Frag { float c[4][4][4]; };

__device__ __forceinline__ void mma_mainloop(const float* __restrict__ A,
                                             const float* __restrict__ WT,
                                             int K, int row0, int col0,
                                             float* sm, Frag& F)
{
    int tid  = threadIdx.x;
    int lane = tid & 31, wid = tid >> 5;
    int wm = wid >> 2, wn = wid & 3;
    int group = lane >> 2, tig = lane & 3;

    float* Abuf[2] = { sm,            sm + STAGEF };
    float* Bbuf[2] = { sm + ASZ,      sm + STAGEF + ASZ };

    // loader geometry: float4 idx = tid + i*256 -> row = (tid>>3)+32i, c4 = tid&7
    int r0 = tid >> 3;
    int c4 = tid & 7;
    const float* gA = A  + (size_t)(row0 + r0) * K + c4 * 4;
    const float* gB = WT + (size_t)(col0 + r0) * K + c4 * 4;

    uint32_t dA[2][4], dB[2][4];
    #pragma unroll
    for (int s = 0; s < 2; s++)
        #pragma unroll
        for (int i = 0; i < 4; i++) {
            dA[s][i] = smem_u32(Abuf[s] + (r0 + 32 * i) * LDAs + c4 * 4);
            dB[s][i] = smem_u32(Bbuf[s] + (r0 + 32 * i) * LDAs + c4 * 4);
        }

    #pragma unroll
    for (int mf = 0; mf < 4; mf++)
        #pragma unroll
        for (int nf = 0; nf < 4; nf++)
            #pragma unroll
            for (int r = 0; r < 4; r++) F.c[mf][nf][r] = 0.f;

    int nk = K >> 5;

    // prologue: stage 0
    #pragma unroll
    for (int i = 0; i < 4; i++) CP_ASYNC(dA[0][i], gA + (size_t)(32 * i) * K);
    #pragma unroll
    for (int i = 0; i < 4; i++) CP_ASYNC(dB[0][i], gB + (size_t)(32 * i) * K);
    CP_COMMIT();

    for (int kt = 0; kt < nk; kt++) {
        int buf = kt & 1;
        if (kt + 1 < nk) {
            int nb = buf ^ 1;
            const float* a = gA + (size_t)(kt + 1) * BKg;
            const float* b = gB + (size_t)(kt + 1) * BKg;
            #pragma unroll
            for (int i = 0; i < 4; i++) CP_ASYNC(dA[nb][i], a + (size_t)(32 * i) * K);
            #pragma unroll
            for (int i = 0; i < 4; i++) CP_ASYNC(dB[nb][i], b + (size_t)(32 * i) * K);
            CP_COMMIT();
            CP_WAIT1();
        } else {
            CP_WAIT0();
        }
        __syncthreads();

        const float* as = Abuf[buf];
        const float* bs = Bbuf[buf];
        #pragma unroll
        for (int ks = 0; ks < 4; ks++) {
            int kb = ks * 8;
            uint32_t b0[4], b1[4];
            #pragma unroll
            for (int nf = 0; nf < 4; nf++) {
                int n = wn * 32 + nf * 8 + group;
                b0[nf] = __float_as_uint(bs[n * LDAs + kb + tig]);
                b1[nf] = __float_as_uint(bs[n * LDAs + kb + tig + 4]);
            }
            #pragma unroll
            for (int mf = 0; mf < 4; mf++) {
                int m = wm * 64 + mf * 16 + group;
                uint32_t a0 = __float_as_uint(as[m * LDAs + kb + tig]);
                uint32_t a1 = __float_as_uint(as[(m + 8) * LDAs + kb + tig]);
                uint32_t a2 = __float_as_uint(as[m * LDAs + kb + tig + 4]);
                uint32_t a3 = __float_as_uint(as[(m + 8) * LDAs + kb + tig + 4]);
                #pragma unroll
                for (int nf = 0; nf < 4; nf++)
                    mma_tf32(F.c[mf][nf], a0, a1, a2, a3, b0[nf], b1[nf]);
            }
        }
        __syncthreads();
    }
}

// QKV: gridDim.z selects W/bias/output; epilogue writes head-permuted [B*H, L, 64]
__global__ __launch_bounds__(256, 2)
void tc_gemm_qkv(const float* __restrict__ A,
                 const float* __restrict__ Wqt, const float* __restrict__ Wkt,
                 const float* __restrict__ Wvt,
                 const float* __restrict__ bq, const float* __restrict__ bk,
                 const float* __restrict__ bv,
                 float* __restrict__ Cq, float* __restrict__ Ck, float* __restrict__ Cv)
{
    extern __shared__ float sm[];
    int z = blockIdx.z;
    const float* WT   = (z == 0) ? Wqt : (z == 1) ? Wkt : Wvt;
    const float* bias = (z == 0) ? bq  : (z == 1) ? bk  : bv;
    float* C          = (z == 0) ? Cq  : (z == 1) ? Ck  : Cv;

    int row0 = blockIdx.y * BM;
    int col0 = blockIdx.x * BN;
    Frag F;
    mma_mainloop(A, WT, D_MODEL, row0, col0, sm, F);

    int lane = threadIdx.x & 31, wid = threadIdx.x >> 5;
    int wm = wid >> 2, wn = wid & 3;
    int group = lane >> 2, tig = lane & 3;

    #pragma unroll
    for (int mf = 0; mf < 4; mf++) {
        #pragma unroll
        for (int nf = 0; nf < 4; nf++) {
            int row = row0 + wm * 64 + mf * 16 + group;
            int col = col0 + wn * 32 + nf * 8 + 2 * tig;
            float2 bv2 = *(const float2*)(bias + col);
            int h = col >> 6, d = col & 63;
            #pragma unroll
            for (int half = 0; half < 2; half++) {
                int r = row + half * 8;
                int b = r >> 11, l = r & (SEQ - 1);
                float2 o;
                o.x = F.c[mf][nf][half * 2 + 0] + bv2.x;
                o.y = F.c[mf][nf][half * 2 + 1] + bv2.y;
                *(float2*)(C + (((size_t)(b * NHEAD + h) * SEQ) + l) * HEAD_DIM + d) = o;
            }
        }
    }
}

// MODE 1: gelu(acc+bias) tf32-rounded.  MODE 2: res + acc + bias.
template<int MODE>
__global__ __launch_bounds__(256, 2)
void tc_gemm(const float* __restrict__ A, const float* __restrict__ WT,
             const float* __restrict__ bias, const float* __restrict__ res,
             float* __restrict__ C, int N, int K)
{
    extern __shared__ float sm[];
    int row0 = blockIdx.y * BM;
    int col0 = blockIdx.x * BN;
    Frag F;
    mma_mainloop(A, WT, K, row0, col0, sm, F);

    int lane = threadIdx.x & 31, wid = threadIdx.x >> 5;
    int wm = wid >> 2, wn = wid & 3;
    int group = lane >> 2, tig = lane & 3;

    #pragma unroll
    for (int mf = 0; mf < 4; mf++) {
        #pragma unroll
        for (int nf = 0; nf < 4; nf++) {
            int row = row0 + wm * 64 + mf * 16 + group;
            int col = col0 + wn * 32 + nf * 8 + 2 * tig;
            float2 bv2 = *(const float2*)(bias + col);
            #pragma unroll
            for (int half = 0; half < 2; half++) {
                int r = row + half * 8;
                float2 o;
                o.x = F.c[mf][nf][half * 2 + 0] + bv2.x;
                o.y = F.c[mf][nf][half * 2 + 1] + bv2.y;
                if (MODE == 1) {
                    o.x = tf32r(gelu_exact(o.x));
                    o.y = tf32r(gelu_exact(o.y));
                } else {
                    float2 r2 = *(const float2*)(res + (size_t)r * N + col);
                    o.x += r2.x; o.y += r2.y;
                }
                *(float2*)(C + (size_t)r * N + col) = o;
            }
        }
    }
}

// ---------------------------------------------------------------------------
// Flash-style causal attention (SIMT fp32; output tf32-rounded)
// ---------------------------------------------------------------------------
#define ATTN_PAD 65
#define ATTN_SMEM (4 * 64 * ATTN_PAD * (int)sizeof(float))

__global__ __launch_bounds__(256)
void attn_kernel(const float* __restrict__ Q, const float* __restrict__ K,
                 const float* __restrict__ V, float* __restrict__ out)
{
    extern __shared__ float sm[];
    float (*Qs)[ATTN_PAD] = (float(*)[ATTN_PAD])(sm);
    float (*Ks)[ATTN_PAD] = (float(*)[ATTN_PAD])(sm + 64 * ATTN_PAD);
    float (*Vs)[ATTN_PAD] = (float(*)[ATTN_PAD])(sm + 2 * 64 * ATTN_PAD);
    float (*Ps)[ATTN_PAD] = (float(*)[ATTN_PAD])(sm + 3 * 64 * ATTN_PAD);

    int qt  = blockIdx.x;
    int bh  = blockIdx.y;
    int tid = threadIdx.x;
    int tx = tid & 15, ty = tid >> 4;

    const float* Qb = Q + (size_t)bh * SEQ * HEAD_DIM;
    const float* Kb = K + (size_t)bh * SEQ * HEAD_DIM;
    const float* Vb = V + (size_t)bh * SEQ * HEAD_DIM;

    #pragma unroll
    for (int i = 0; i < 16; i++) {
        int e = tid + i * 256;
        int r = e >> 6, c = e & 63;
        Qs[r][c] = Qb[(size_t)(qt * 64 + r) * HEAD_DIM + c];
    }

    float acc[4][4];
    float m_i[4], l_i[4];
    #pragma unroll
    for (int i = 0; i < 4; i++) {
        m_i[i] = -1e30f; l_i[i] = 0.f;
        #pragma unroll
        for (int j = 0; j < 4; j++) acc[i][j] = 0.f;
    }
    const float scale = 0.125f;

    for (int kt = 0; kt <= qt; kt++) {
        __syncthreads();
        #pragma unroll
        for (int i = 0; i < 16; i++) {
            int e = tid + i * 256;
            int r = e >> 6, c = e & 63;
            Ks[r][c] = Kb[(size_t)(kt * 64 + r) * HEAD_DIM + c];
            Vs[r][c] = Vb[(size_t)(kt * 64 + r) * HEAD_DIM + c];
        }
        __syncthreads();

        float s[4][4];
        #pragma unroll
        for (int i = 0; i < 4; i++)
            #pragma unroll
            for (int j = 0; j < 4; j++) s[i][j] = 0.f;

        for (int d = 0; d < 64; d++) {
            float a0 = Qs[ty*4+0][d], a1 = Qs[ty*4+1][d];
            float a2 = Qs[ty*4+2][d], a3 = Qs[ty*4+3][d];
            float q0 = Ks[tx*4+0][d], q1 = Ks[tx*4+1][d];
            float q2 = Ks[tx*4+2][d], q3 = Ks[tx*4+3][d];
            s[0][0] = fmaf(a0,q0,s[0][0]); s[0][1] = fmaf(a0,q1,s[0][1]);
            s[0][2] = fmaf(a0,q2,s[0][2]); s[0][3] = fmaf(a0,q3,s[0][3]);
            s[1][0] = fmaf(a1,q0,s[1][0]); s[1][1] = fmaf(a1,q1,s[1][1]);
            s[1][2] = fmaf(a1,q2,s[1][2]); s[1][3] = fmaf(a1,q3,s[1][3]);
            s[2][0] = fmaf(a2,q0,s[2][0]); s[2][1] = fmaf(a2,q1,s[2][1]);
            s[2][2] = fmaf(a2,q2,s[2][2]); s[2][3] = fmaf(a2,q3,s[2][3]);
            s[3][0] = fmaf(a3,q0,s[3][0]); s[3][1] = fmaf(a3,q1,s[3][1]);
            s[3][2] = fmaf(a3,q2,s[3][2]); s[3][3] = fmaf(a3,q3,s[3][3]);
        }

        if (kt == qt) {
            #pragma unroll
            for (int i = 0; i < 4; i++)
                #pragma unroll
                for (int j = 0; j < 4; j++) {
                    int qg = ty * 4 + i, kg = tx * 4 + j;
                    s[i][j] = (kg > qg) ? -1e30f : s[i][j] * scale;
                }
        } else {
            #pragma unroll
            for (int i = 0; i < 4; i++)
                #pragma unroll
                for (int j = 0; j < 4; j++) s[i][j] *= scale;
        }

        #pragma unroll
        for (int i = 0; i < 4; i++) {
            float mx = fmaxf(fmaxf(s[i][0], s[i][1]), fmaxf(s[i][2], s[i][3]));
            #pragma unroll
            for (int o = 8; o > 0; o >>= 1)
                mx = fmaxf(mx, __shfl_xor_sync(0xffffffffu, mx, o));
            float mnew = fmaxf(m_i[i], mx);
            float corr = __expf(m_i[i] - mnew);
            float rsum = 0.f;
            #pragma unroll
            for (int j = 0; j < 4; j++) {
                float p = __expf(s[i][j] - mnew);
                s[i][j] = p;
                rsum += p;
            }
            #pragma unroll
            for (int o = 8; o > 0; o >>= 1)
                rsum += __shfl_xor_sync(0xffffffffu, rsum, o);
            l_i[i] = l_i[i] * corr + rsum;
            m_i[i] = mnew;
            #pragma unroll
            for (int j = 0; j < 4; j++) {
                acc[i][j] *= corr;
                Ps[ty*4+i][tx*4+j] = s[i][j];
            }
        }
        __syncthreads();

        for (int k = 0; k < 64; k++) {
            float p0 = Ps[ty*4+0][k], p1 = Ps[ty*4+1][k];
            float p2 = Ps[ty*4+2][k], p3 = Ps[ty*4+3][k];
            float v0 = Vs[k][tx*4+0], v1 = Vs[k][tx*4+1];
            float v2 = Vs[k][tx*4+2], v3 = Vs[k][tx*4+3];
            acc[0][0] = fmaf(p0,v0,acc[0][0]); acc[0][1] = fmaf(p0,v1,acc[0][1]);
            acc[0][2] = fmaf(p0,v2,acc[0][2]); acc[0][3] = fmaf(p0,v3,acc[0][3]);
            acc[1][0] = fmaf(p1,v0,acc[1][0]); acc[1][1] = fmaf(p1,v1,acc[1][1]);
            acc[1][2] = fmaf(p1,v2,acc[1][2]); acc[1][3] = fmaf(p1,v3,acc[1][3]);
            acc[2][0] = fmaf(p2,v0,acc[2][0]); acc[2][1] = fmaf(p2,v1,acc[2][1]);
            acc[2][2] = fmaf(p2,v2,acc[2][2]); acc[2][3] = fmaf(p2,v3,acc[2][3]);
            acc[3][0] = fmaf(p3,v0,acc[3][0]); acc[3][1] = fmaf(p3,v1,acc[3][1]);
            acc[3][2] = fmaf(p3,v2,acc[3][2]); acc[3][3] = fmaf(p3,v3,acc[3][3]);
        }
    }

    int b = bh >> 4, h = bh & 15;
    #pragma unroll
    for (int i = 0; i < 4; i++) {
        float inv_l = 1.0f / l_i[i];
        int l = qt * 64 + ty * 4 + i;
        #pragma unroll
        for (int j = 0; j < 4; j++) {
            int d = tx * 4 + j;
            out[((size_t)(b * SEQ + l)) * D_MODEL + h * HEAD_DIM + d] = tf32r(acc[i][j] * inv_l);
        }
    }
}

// ---------------------------------------------------------------------------
// Launch
// ---------------------------------------------------------------------------
extern "C" void kernel_launch(void* const* d_in, const int* in_sizes, int n_in,
                              void* d_out, int out_size)
{
    const float* x   = (const float*)d_in[0];
    const float* Wq  = (const float*)d_in[2];
    const float* bq  = (const float*)d_in[3];
    const float* Wk  = (const float*)d_in[4];
    const float* bk  = (const float*)d_in[5];
    const float* Wv  = (const float*)d_in[6];
    const float* bv  = (const float*)d_in[7];
    const float* Wo  = (const float*)d_in[8];
    const float* bo  = (const float*)d_in[9];
    const float* g1  = (const float*)d_in[10];
    const float* b1  = (const float*)d_in[11];
    const float* g2  = (const float*)d_in[12];
    const float* b2  = (const float*)d_in[13];
    const float* W1  = (const float*)d_in[14];
    const float* bf1 = (const float*)d_in[15];
    const float* W2  = (const float*)d_in[16];
    const float* bf2 = (const float*)d_in[17];
    float* out = (float*)d_out;

    float *p_nx, *p_q, *p_k, *p_v, *p_attn, *p_x1, *p_nx2, *p_ffh;
    float *p_wqt, *p_wkt, *p_wvt, *p_wot, *p_w1t, *p_w2t;
    cudaGetSymbolAddress((void**)&p_nx,   g_nx);
    cudaGetSymbolAddress((void**)&p_q,    g_q);
    cudaGetSymbolAddress((void**)&p_k,    g_k);
    cudaGetSymbolAddress((void**)&p_v,    g_v);
    cudaGetSymbolAddress((void**)&p_attn, g_attn);
    cudaGetSymbolAddress((void**)&p_x1,   g_x1);
    cudaGetSymbolAddress((void**)&p_nx2,  g_nx2);
    cudaGetSymbolAddress((void**)&p_ffh,  g_ffh);
    cudaGetSymbolAddress((void**)&p_wqt,  g_wqt);
    cudaGetSymbolAddress((void**)&p_wkt,  g_wkt);
    cudaGetSymbolAddress((void**)&p_wvt,  g_wvt);
    cudaGetSymbolAddress((void**)&p_wot,  g_wot);
    cudaGetSymbolAddress((void**)&p_w1t,  g_w1t);
    cudaGetSymbolAddress((void**)&p_w2t,  g_w2t);

    cudaFuncSetAttribute(attn_kernel, cudaFuncAttributeMaxDynamicSharedMemorySize, ATTN_SMEM);
    cudaFuncSetAttribute(tc_gemm_qkv, cudaFuncAttributeMaxDynamicSharedMemorySize, GEMM_SMEM);
    cudaFuncSetAttribute(tc_gemm<1>,  cudaFuncAttributeMaxDynamicSharedMemorySize, GEMM_SMEM);
    cudaFuncSetAttribute(tc_gemm<2>,  cudaFuncAttributeMaxDynamicSharedMemorySize, GEMM_SMEM);

    dim3 t256(256);
    dim3 t32x8(32, 8);

    // 0. transpose + tf32-round weights
    transpose_kernel<<<dim3(D_MODEL/32, D_MODEL/32), t32x8>>>(Wq, p_wqt, D_MODEL, D_MODEL);
    transpose_kernel<<<dim3(D_MODEL/32, D_MODEL/32), t32x8>>>(Wk, p_wkt, D_MODEL, D_MODEL);
    transpose_kernel<<<dim3(D_MODEL/32, D_MODEL/32), t32x8>>>(Wv, p_wvt, D_MODEL, D_MODEL);
    transpose_kernel<<<dim3(D_MODEL/32, D_MODEL/32), t32x8>>>(Wo, p_wot, D_MODEL, D_MODEL);
    transpose_kernel<<<dim3(D_FF/32,    D_MODEL/32), t32x8>>>(W1, p_w1t, D_MODEL, D_FF);
    transpose_kernel<<<dim3(D_MODEL/32, D_FF/32),    t32x8>>>(W2, p_w2t, D_FF,    D_MODEL);

    // 1. nx = LN1(x)
    ln_kernel<<<MROWS, t256>>>(x, g1, b1, p_nx);

    // 2. Q/K/V (one fused launch)
    dim3 gQKV(D_MODEL / BN, MROWS / BM, 3);
    tc_gemm_qkv<<<gQKV, t256, GEMM_SMEM>>>(p_nx, p_wqt, p_wkt, p_wvt,
                                           bq, bk, bv, p_q, p_k, p_v);

    // 3. causal flash attention
    dim3 gAttn(SEQ / 64, BATCH * NHEAD);
    attn_kernel<<<gAttn, t256, ATTN_SMEM>>>(p_q, p_k, p_v, p_attn);

    // 4. x1 = x + attn @ Wo + bo
    dim3 gD(D_MODEL / BN, MROWS / BM);
    tc_gemm<2><<<gD, t256, GEMM_SMEM>>>(p_attn, p_wot, bo, x, p_x1, D_MODEL, D_MODEL);

    // 5. nx2 = LN2(x1)
    ln_kernel<<<MROWS, t256>>>(p_x1, g2, b2, p_nx2);

    // 6. h = gelu(nx2 @ W1 + bf1)
    dim3 gF1(D_FF / BN, MROWS / BM);
    tc_gemm<1><<<gF1, t256, GEMM_SMEM>>>(p_nx2, p_w1t, bf1, nullptr, p_ffh, D_FF, D_MODEL);

    // 7. out = x1 + h @ W2 + bf2
    tc_gemm<2><<<gD, t256, GEMM_SMEM>>>(p_ffh, p_w2t, bf2, p_x1, out, D_MODEL, D_FF);
}

// round 5
// speedup vs baseline: 4.4192x; 2.2406x over previous
#include <cuda_runtime.h>
#include <cuda_fp16.h>
#include <math.h>
#include <stdint.h>

#define D_MODEL 1024
#define NHEAD   16
#define HEAD_DIM 64
#define D_FF    4096
#define BATCH   2
#define SEQ     2048
#define MROWS   (BATCH * SEQ)   // 4096
#define LN_EPS  1e-5f

// ---------------------------------------------------------------------------
// Scratch (device globals)
// ---------------------------------------------------------------------------
__device__ __half g_nx  [MROWS * D_MODEL];
__device__ __half g_q   [MROWS * D_MODEL];   // [B*H, L, 64]
__device__ __half g_k   [MROWS * D_MODEL];
__device__ __half g_v   [MROWS * D_MODEL];
__device__ __half g_attn[MROWS * D_MODEL];   // [B, L, D]
__device__ float  g_x1  [MROWS * D_MODEL];
__device__ __half g_nx2 [MROWS * D_MODEL];
__device__ __half g_ffh [MROWS * D_FF];
__device__ __half g_wqt [D_MODEL * D_MODEL]; // [N][K]
__device__ __half g_wkt [D_MODEL * D_MODEL];
__device__ __half g_wvt [D_MODEL * D_MODEL];
__device__ __half g_wot [D_MODEL * D_MODEL];
__device__ __half g_w1t [D_MODEL * D_FF];
__device__ __half g_w2t [D_MODEL * D_FF];

// ---------------------------------------------------------------------------
// Helpers
// ---------------------------------------------------------------------------
__device__ __forceinline__ uint32_t smem_u32(const void* p) {
    uint32_t a;
    asm("{ .reg .u64 t; cvta.to.shared.u64 t, %1; cvt.u32.u64 %0, t; }" : "=r"(a) : "l"(p));
    return a;
}
__device__ __forceinline__ uint32_t h2_as_u32(__half2 h) {
    return *reinterpret_cast<uint32_t*>(&h);
}
__device__ __forceinline__ uint32_t pack_f2h2(float lo, float hi) {
    uint32_t r;
    asm("cvt.rn.f16x2.f32 %0, %1, %2;" : "=r"(r) : "f"(hi), "f"(lo));
    return r;
}
__device__ __forceinline__ float gelu_exact(float v) {
    return 0.5f * v * (1.0f + erff(v * 0.70710678118654752f));
}

#define CP_ASYNC(dst, src) \
    asm volatile("cp.async.cg.shared.global [%0], [%1], 16;" :: "r"(dst), "l"(src))
#define CP_COMMIT() asm volatile("cp.async.commit_group;")
#define CP_WAIT1()  asm volatile("cp.async.wait_group 1;")
#define CP_WAIT0()  asm volatile("cp.async.wait_group 0;")

__device__ __forceinline__ void mma_f16(float* c,
    uint32_t a0, uint32_t a1, uint32_t a2, uint32_t a3, uint32_t b0, uint32_t b1)
{
    asm volatile(
        "mma.sync.aligned.m16n8k16.row.col.f32.f16.f16.f32 "
        "{%0,%1,%2,%3}, {%4,%5,%6,%7}, {%8,%9}, {%0,%1,%2,%3};"
        : "+f"(c[0]), "+f"(c[1]), "+f"(c[2]), "+f"(c[3])
        : "r"(a0), "r"(a1), "r"(a2), "r"(a3), "r"(b0), "r"(b1));
}

// ---------------------------------------------------------------------------
// Weight transpose (fp32 [K][N] -> half [N][K])
// ---------------------------------------------------------------------------
__global__ void transpose_kernel(const float* __restrict__ in, __half* __restrict__ out,
                                 int K, int N)
{
    __shared__ float tile[32][33];
    int x = blockIdx.x * 32 + threadIdx.x;
    int y0 = blockIdx.y * 32;
    #pragma unroll
    for (int i = threadIdx.y; i < 32; i += 8)
        tile[i][threadIdx.x] = in[(size_t)(y0 + i) * N + x];
    __syncthreads();
    int xo = blockIdx.y * 32 + threadIdx.x;
    int yo0 = blockIdx.x * 32;
    #pragma unroll
    for (int i = threadIdx.y; i < 32; i += 8)
        out[(size_t)(yo0 + i) * K + xo] = __float2half(tile[threadIdx.x][i]);
}

// ---------------------------------------------------------------------------
// LayerNorm: fp32 in, half out
// ---------------------------------------------------------------------------
__global__ void ln_kernel(const float* __restrict__ x, const float* __restrict__ g,
                          const float* __restrict__ b, __half* __restrict__ out)
{
    int row = blockIdx.x;
    int tid = threadIdx.x;
    const float* xr = x + (size_t)row * D_MODEL;
    int c = tid * 4;
    float4 v = *(const float4*)(xr + c);

    float s  = v.x + v.y + v.z + v.w;
    float ss = v.x*v.x + v.y*v.y + v.z*v.z + v.w*v.w;
    #pragma unroll
    for (int o = 16; o > 0; o >>= 1) {
        s  += __shfl_xor_sync(0xffffffffu, s,  o);
        ss += __shfl_xor_sync(0xffffffffu, ss, o);
    }
    __shared__ float smS[8], smSS[8];
    int w = tid >> 5, lane = tid & 31;
    if (lane == 0) { smS[w] = s; smSS[w] = ss; }
    __syncthreads();
    float tot = 0.f, tot2 = 0.f;
    #pragma unroll
    for (int i = 0; i < 8; i++) { tot += smS[i]; tot2 += smSS[i]; }

    float mu   = tot  * (1.0f / D_MODEL);
    float var  = tot2 * (1.0f / D_MODEL) - mu * mu;
    float rstd = rsqrtf(var + LN_EPS);

    float4 gv = *(const float4*)(g + c);
    float4 bv = *(const float4*)(b + c);
    __half2* o2 = (__half2*)(out + (size_t)row * D_MODEL + c);
    o2[0] = __floats2half2_rn((v.x - mu) * rstd * gv.x + bv.x,
                              (v.y - mu) * rstd * gv.y + bv.y);
    o2[1] = __floats2half2_rn((v.z - mu) * rstd * gv.z + bv.z,
                              (v.w - mu) * rstd * gv.w + bv.w);
}

// ---------------------------------------------------------------------------
// fp16 mma GEMM: C[M,N] = A[M,K] @ WT[N,K]^T   (A, WT half; accum fp32)
// BM=BN=128, BK=32 (halves), 256 thr (8 warps 2x4), warp 64x32, m16n8k16.
// ---------------------------------------------------------------------------
#define BM 128
#define BN 128
#define BKh 32
#define LDH 40                       // halves per smem row (32 + 8 pad)
#define ASZH (BM * LDH)              // halves per A stage
#define STAGEH (2 * ASZH)            // A + B per stage
#define GEMM_SMEM (2 * STAGEH * 2)   // bytes = 40960

struct Frag { float c[4][4][4]; };

__device__ __forceinline__ void mma_mainloop(const __half* __restrict__ A,
                                             const __half* __restrict__ WT,
                                             int K, int row0, int col0,
                                             __half* sm, Frag& F)
{
    int tid  = threadIdx.x;
    int lane = tid & 31, wid = tid >> 5;
    int wm = wid >> 2, wn = wid & 3;
    int group = lane >> 2, tig = lane & 3;

    __half* Abuf[2] = { sm,           sm + STAGEH };
    __half* Bbuf[2] = { sm + ASZH,    sm + STAGEH + ASZH };

    // loader: chunk = 8 halves; per row 4 chunks; r = tid>>2 (+64), c8 = tid&3
    int r0 = tid >> 2;
    int c8 = tid & 3;
    const __half* gA = A  + (size_t)(row0 + r0) * K + c8 * 8;
    const __half* gB = WT + (size_t)(col0 + r0) * K + c8 * 8;

    uint32_t dA[2][2], dB[2][2];
    #pragma unroll
    for (int s = 0; s < 2; s++)
        #pragma unroll
        for (int i = 0; i < 2; i++) {
            dA[s][i] = smem_u32(Abuf[s] + (r0 + 64 * i) * LDH + c8 * 8);
            dB[s][i] = smem_u32(Bbuf[s] + (r0 + 64 * i) * LDH + c8 * 8);
        }

    #pragma unroll
    for (int mf = 0; mf < 4; mf++)
        #pragma unroll
        for (int nf = 0; nf < 4; nf++)
            #pragma unroll
            for (int r = 0; r < 4; r++) F.c[mf][nf][r] = 0.f;

    int nk = K / BKh;

    #pragma unroll
    for (int i = 0; i < 2; i++) CP_ASYNC(dA[0][i], gA + (size_t)(64 * i) * K);
    #pragma unroll
    for (int i = 0; i < 2; i++) CP_ASYNC(dB[0][i], gB + (size_t)(64 * i) * K);
    CP_COMMIT();

    for (int kt = 0; kt < nk; kt++) {
        int buf = kt & 1;
        if (kt + 1 < nk) {
            int nb = buf ^ 1;
            const __half* a = gA + (size_t)(kt + 1) * BKh;
            const __half* b = gB + (size_t)(kt + 1) * BKh;
            #pragma unroll
            for (int i = 0; i < 2; i++) CP_ASYNC(dA[nb][i], a + (size_t)(64 * i) * K);
            #pragma unroll
            for (int i = 0; i < 2; i++) CP_ASYNC(dB[nb][i], b + (size_t)(64 * i) * K);
            CP_COMMIT();
            CP_WAIT1();
        } else {
            CP_WAIT0();
        }
        __syncthreads();

        const __half* as = Abuf[buf];
        const __half* bs = Bbuf[buf];
        #pragma unroll
        for (int ks = 0; ks < 2; ks++) {
            int kb = ks * 16;
            uint32_t b0[4], b1[4];
            #pragma unroll
            for (int nf = 0; nf < 4; nf++) {
                int n = wn * 32 + nf * 8 + group;
                b0[nf] = *(const uint32_t*)(bs + n * LDH + kb + 2 * tig);
                b1[nf] = *(const uint32_t*)(bs + n * LDH + kb + 2 * tig + 8);
            }
            #pragma unroll
            for (int mf = 0; mf < 4; mf++) {
                int m = wm * 64 + mf * 16 + group;
                uint32_t a0 = *(const uint32_t*)(as + m * LDH + kb + 2 * tig);
                uint32_t a1 = *(const uint32_t*)(as + (m + 8) * LDH + kb + 2 * tig);
                uint32_t a2 = *(const uint32_t*)(as + m * LDH + kb + 2 * tig + 8);
                uint32_t a3 = *(const uint32_t*)(as + (m + 8) * LDH + kb + 2 * tig + 8);
                #pragma unroll
                for (int nf = 0; nf < 4; nf++)
                    mma_f16(F.c[mf][nf], a0, a1, a2, a3, b0[nf], b1[nf]);
            }
        }
        __syncthreads();
    }
}

// QKV: gridDim.z selects weight; writes head-permuted half [B*H, L, 64]
__global__ __launch_bounds__(256, 2)
void tc_gemm_qkv(const __half* __restrict__ A,
                 const __half* __restrict__ Wqt, const __half* __restrict__ Wkt,
                 const __half* __restrict__ Wvt,
                 const float* __restrict__ bq, const float* __restrict__ bk,
                 const float* __restrict__ bv,
                 __half* __restrict__ Cq, __half* __restrict__ Ck, __half* __restrict__ Cv)
{
    extern __shared__ __half sm[];
    int z = blockIdx.z;
    const __half* WT  = (z == 0) ? Wqt : (z == 1) ? Wkt : Wvt;
    const float* bias = (z == 0) ? bq  : (z == 1) ? bk  : bv;
    __half* C         = (z == 0) ? Cq  : (z == 1) ? Ck  : Cv;

    int row0 = blockIdx.y * BM;
    int col0 = blockIdx.x * BN;
    Frag F;
    mma_mainloop(A, WT, D_MODEL, row0, col0, sm, F);

    int lane = threadIdx.x & 31, wid = threadIdx.x >> 5;
    int wm = wid >> 2, wn = wid & 3;
    int group = lane >> 2, tig = lane & 3;

    #pragma unroll
    for (int mf = 0; mf < 4; mf++) {
        #pragma unroll
        for (int nf = 0; nf < 4; nf++) {
            int row = row0 + wm * 64 + mf * 16 + group;
            int col = col0 + wn * 32 + nf * 8 + 2 * tig;
            float2 bv2 = *(const float2*)(bias + col);
            int h = col >> 6, d = col & 63;
            #pragma unroll
            for (int half2i = 0; half2i < 2; half2i++) {
                int r = row + half2i * 8;
                int b = r >> 11, l = r & (SEQ - 1);
                __half2 o = __floats2half2_rn(F.c[mf][nf][half2i * 2 + 0] + bv2.x,
                                              F.c[mf][nf][half2i * 2 + 1] + bv2.y);
                *(__half2*)(C + (((size_t)(b * NHEAD + h) * SEQ) + l) * HEAD_DIM + d) = o;
            }
        }
    }
}

// MODE 1: half out = gelu(acc+bias).  MODE 2: float out = res + acc + bias.
template<int MODE>
__global__ __launch_bounds__(256, 2)
void tc_gemm(const __half* __restrict__ A, const __half* __restrict__ WT,
             const float* __restrict__ bias, const float* __restrict__ res,
             void* __restrict__ Cv, int N, int K)
{
    extern __shared__ __half sm[];
    int row0 = blockIdx.y * BM;
    int col0 = blockIdx.x * BN;
    Frag F;
    mma_mainloop(A, WT, K, row0, col0, sm, F);

    int lane = threadIdx.x & 31, wid = threadIdx.x >> 5;
    int wm = wid >> 2, wn = wid & 3;
    int group = lane >> 2, tig = lane & 3;

    #pragma unroll
    for (int mf = 0; mf < 4; mf++) {
        #pragma unroll
        for (int nf = 0; nf < 4; nf++) {
            int row = row0 + wm * 64 + mf * 16 + group;
            int col = col0 + wn * 32 + nf * 8 + 2 * tig;
            float2 bv2 = *(const float2*)(bias + col);
            #pragma unroll
            for (int hi = 0; hi < 2; hi++) {
                int r = row + hi * 8;
                float ox = F.c[mf][nf][hi * 2 + 0] + bv2.x;
                float oy = F.c[mf][nf][hi * 2 + 1] + bv2.y;
                if (MODE == 1) {
                    __half2 o = __floats2half2_rn(gelu_exact(ox), gelu_exact(oy));
                    *(__half2*)((__half*)Cv + (size_t)r * N + col) = o;
                } else {
                    float2 r2 = *(const float2*)(res + (size_t)r * N + col);
                    float2 o; o.x = ox + r2.x; o.y = oy + r2.y;
                    *(float2*)((float*)Cv + (size_t)r * N + col) = o;
                }
            }
        }
    }
}

// ---------------------------------------------------------------------------
// fp16 mma flash attention (causal).
// Block: 128 q rows, 8 warps (m16 each), key tiles of 64. Grid (L/128, B*H).
// ---------------------------------------------------------------------------
__global__ __launch_bounds__(256)
void attn_kernel(const __half* __restrict__ Q, const __half* __restrict__ K,
                 const __half* __restrict__ V, __half* __restrict__ out)
{
    __shared__ __half Qs[128][72];
    __shared__ __half Ks[64][72];
    __shared__ __half Vt[64][72];   // transposed: [d][key]

    int tid = threadIdx.x;
    int lane = tid & 31, wid = tid >> 5;
    int group = lane >> 2, tig = lane & 3;
    int qb = blockIdx.x * 128;
    int bh = blockIdx.y;
    int wb = wid * 16;

    const __half* Qb = Q + (size_t)bh * SEQ * HEAD_DIM;
    const __half* Kb = K + (size_t)bh * SEQ * HEAD_DIM;
    const __half* Vb = V + (size_t)bh * SEQ * HEAD_DIM;

    // load Q tile: 128x64 halves via 16B chunks (8 chunks/row)
    #pragma unroll
    for (int i = 0; i < 4; i++) {
        int e = tid + i * 256;
        int r = e >> 3, c = e & 7;
        *(uint4*)&Qs[r][c * 8] = *(const uint4*)(Qb + (size_t)(qb + r) * HEAD_DIM + c * 8);
    }
    __syncthreads();

    // Q fragments, register-resident: 4 ksteps x 4 regs
    uint32_t qa[4][4];
    #pragma unroll
    for (int ks = 0; ks < 4; ks++) {
        int kb = ks * 16 + 2 * tig;
        qa[ks][0] = *(const uint32_t*)&Qs[wb + group][kb];
        qa[ks][1] = *(const uint32_t*)&Qs[wb + group + 8][kb];
        qa[ks][2] = *(const uint32_t*)&Qs[wb + group][kb + 8];
        qa[ks][3] = *(const uint32_t*)&Qs[wb + group + 8][kb + 8];
    }

    float o[8][4];
    #pragma unroll
    for (int i = 0; i < 8; i++)
        #pragma unroll
        for (int j = 0; j < 4; j++) o[i][j] = 0.f;
    float m2[2] = {-1e30f, -1e30f};
    float l2[2] = {0.f, 0.f};

    const float scale = 0.125f;
    int row_g0 = qb + wb + group;       // thread's row (c0,c1); +8 for (c2,c3)
    int nkt = (qb >> 6) + 2;

    for (int kt = 0; kt < nkt; kt++) {
        __syncthreads();
        // load K tile (64x64)
        #pragma unroll
        for (int i = 0; i < 2; i++) {
            int e = tid + i * 256;
            int r = e >> 3, c = e & 7;
            *(uint4*)&Ks[r][c * 8] = *(const uint4*)(Kb + (size_t)(kt * 64 + r) * HEAD_DIM + c * 8);
        }
        // load V tile transposed: Vt[d][key]
        #pragma unroll
        for (int i = 0; i < 8; i++) {
            int e = tid + i * 256;
            int key = e >> 5, c = e & 31;
            __half2 v2 = *(const __half2*)(Vb + (size_t)(kt * 64 + key) * HEAD_DIM + 2 * c);
            Vt[2 * c][key]     = __low2half(v2);
            Vt[2 * c + 1][key] = __high2half(v2);
        }
        __syncthreads();

        bool active = (kt * 64) <= (qb + wb + 15);
        if (active) {
            // S = Q K^T : 8 key-fragments x 4 ksteps
            float s[8][4];
            #pragma unroll
            for (int nf = 0; nf < 8; nf++)
                #pragma unroll
                for (int c = 0; c < 4; c++) s[nf][c] = 0.f;
            #pragma unroll
            for (int ks = 0; ks < 4; ks++) {
                int kb = ks * 16 + 2 * tig;
                #pragma unroll
                for (int nf = 0; nf < 8; nf++) {
                    uint32_t b0 = *(const uint32_t*)&Ks[nf * 8 + group][kb];
                    uint32_t b1 = *(const uint32_t*)&Ks[nf * 8 + group][kb + 8];
                    mma_f16(s[nf], qa[ks][0], qa[ks][1], qa[ks][2], qa[ks][3], b0, b1);
                }
            }

            // scale + causal mask
            bool need_mask = (kt * 64 + 63) > (qb + wb);
            #pragma unroll
            for (int nf = 0; nf < 8; nf++) {
                #pragma unroll
                for (int c = 0; c < 4; c++) {
                    float v = s[nf][c] * scale;
                    if (need_mask) {
                        int key = kt * 64 + nf * 8 + 2 * tig + (c & 1);
                        int rg  = row_g0 + ((c >= 2) ? 8 : 0);
                        if (key > rg) v = -1e30f;
                    }
                    s[nf][c] = v;
                }
            }

            // online softmax for the 2 rows this thread touches
            #pragma unroll
            for (int r = 0; r < 2; r++) {
                float mx = -1e30f;
                #pragma unroll
                for (int nf = 0; nf < 8; nf++)
                    mx = fmaxf(mx, fmaxf(s[nf][2 * r], s[nf][2 * r + 1]));
                mx = fmaxf(mx, __shfl_xor_sync(0xffffffffu, mx, 1));
                mx = fmaxf(mx, __shfl_xor_sync(0xffffffffu, mx, 2));
                float mnew = fmaxf(m2[r], mx);
                float corr = __expf(m2[r] - mnew);
                float rsum = 0.f;
                #pragma unroll
                for (int nf = 0; nf < 8; nf++) {
                    float p0 = __expf(s[nf][2 * r]     - mnew);
                    float p1 = __expf(s[nf][2 * r + 1] - mnew);
                    s[nf][2 * r] = p0; s[nf][2 * r + 1] = p1;
                    rsum += p0 + p1;
                }
                rsum += __shfl_xor_sync(0xffffffffu, rsum, 1);
                rsum += __shfl_xor_sync(0xffffffffu, rsum, 2);
                l2[r] = l2[r] * corr + rsum;
                m2[r] = mnew;
                #pragma unroll
                for (int nfd = 0; nfd < 8; nfd++) {
                    o[nfd][2 * r]     *= corr;
                    o[nfd][2 * r + 1] *= corr;
                }
            }

            // O += P @ V : pack P (accumulator layout == A-fragment layout)
            #pragma unroll
            for (int ks = 0; ks < 4; ks++) {
                uint32_t pa0 = pack_f2h2(s[2*ks][0],   s[2*ks][1]);
                uint32_t pa1 = pack_f2h2(s[2*ks][2],   s[2*ks][3]);
                uint32_t pa2 = pack_f2h2(s[2*ks+1][0], s[2*ks+1][1]);
                uint32_t pa3 = pack_f2h2(s[2*ks+1][2], s[2*ks+1][3]);
                int kb = ks * 16 + 2 * tig;
                #pragma unroll
                for (int nfd = 0; nfd < 8; nfd++) {
                    uint32_t b0 = *(const uint32_t*)&Vt[nfd * 8 + group][kb];
                    uint32_t b1 = *(const uint32_t*)&Vt[nfd * 8 + group][kb + 8];
                    mma_f16(o[nfd], pa0, pa1, pa2, pa3, b0, b1);
                }
            }
        }
    }

    // write out: [B, L, D], half
    int b = bh >> 4, h = bh & 15;
    float inv0 = 1.0f / l2[0];
    float inv1 = 1.0f / l2[1];
    #pragma unroll
    for (int r = 0; r < 2; r++) {
        int rg = row_g0 + r * 8;
        int l = rg & (SEQ - 1);
        float inv = r ? inv1 : inv0;
        #pragma unroll
        for (int nfd = 0; nfd < 8; nfd++) {
            int d = nfd * 8 + 2 * tig;
            __half2 ov = __floats2half2_rn(o[nfd][2 * r] * inv, o[nfd][2 * r + 1] * inv);
            *(__half2*)(out + ((size_t)(b * SEQ + l)) * D_MODEL + h * HEAD_DIM + d) = ov;
        }
    }
}

// ---------------------------------------------------------------------------
// Launch
// ---------------------------------------------------------------------------
extern "C" void kernel_launch(void* const* d_in, const int* in_sizes, int n_in,
                              void* d_out, int out_size)
{
    const float* x   = (const float*)d_in[0];
    const float* Wq  = (const float*)d_in[2];
    const float* bq  = (const float*)d_in[3];
    const float* Wk  = (const float*)d_in[4];
    const float* bk  = (const float*)d_in[5];
    const float* Wv  = (const float*)d_in[6];
    const float* bv  = (const float*)d_in[7];
    const float* Wo  = (const float*)d_in[8];
    const float* bo  = (const float*)d_in[9];
    const float* g1  = (const float*)d_in[10];
    const float* b1  = (const float*)d_in[11];
    const float* g2  = (const float*)d_in[12];
    const float* b2  = (const float*)d_in[13];
    const float* W1  = (const float*)d_in[14];
    const float* bf1 = (const float*)d_in[15];
    const float* W2  = (const float*)d_in[16];
    const float* bf2 = (const float*)d_in[17];
    float* out = (float*)d_out;

    __half *p_nx, *p_q, *p_k, *p_v, *p_attn, *p_nx2, *p_ffh;
    __half *p_wqt, *p_wkt, *p_wvt, *p_wot, *p_w1t, *p_w2t;
    float *p_x1;
    cudaGetSymbolAddress((void**)&p_nx,   g_nx);
    cudaGetSymbolAddress((void**)&p_q,    g_q);
    cudaGetSymbolAddress((void**)&p_k,    g_k);
    cudaGetSymbolAddress((void**)&p_v,    g_v);
    cudaGetSymbolAddress((void**)&p_attn, g_attn);
    cudaGetSymbolAddress((void**)&p_x1,   g_x1);
    cudaGetSymbolAddress((void**)&p_nx2,  g_nx2);
    cudaGetSymbolAddress((void**)&p_ffh,  g_ffh);
    cudaGetSymbolAddress((void**)&p_wqt,  g_wqt);
    cudaGetSymbolAddress((void**)&p_wkt,  g_wkt);
    cudaGetSymbolAddress((void**)&p_wvt,  g_wvt);
    cudaGetSymbolAddress((void**)&p_wot,  g_wot);
    cudaGetSymbolAddress((void**)&p_w1t,  g_w1t);
    cudaGetSymbolAddress((void**)&p_w2t,  g_w2t);

    cudaFuncSetAttribute(tc_gemm_qkv, cudaFuncAttributeMaxDynamicSharedMemorySize, GEMM_SMEM);
    cudaFuncSetAttribute(tc_gemm<1>,  cudaFuncAttributeMaxDynamicSharedMemorySize, GEMM_SMEM);
    cudaFuncSetAttribute(tc_gemm<2>,  cudaFuncAttributeMaxDynamicSharedMemorySize, GEMM_SMEM);

    dim3 t256(256);
    dim3 t32x8(32, 8);

    // 0. transpose weights to [N][K] half
    transpose_kernel<<<dim3(D_MODEL/32, D_MODEL/32), t32x8>>>(Wq, p_wqt, D_MODEL, D_MODEL);
    transpose_kernel<<<dim3(D_MODEL/32, D_MODEL/32), t32x8>>>(Wk, p_wkt, D_MODEL, D_MODEL);
    transpose_kernel<<<dim3(D_MODEL/32, D_MODEL/32), t32x8>>>(Wv, p_wvt, D_MODEL, D_MODEL);
    transpose_kernel<<<dim3(D_MODEL/32, D_MODEL/32), t32x8>>>(Wo, p_wot, D_MODEL, D_MODEL);
    transpose_kernel<<<dim3(D_FF/32,    D_MODEL/32), t32x8>>>(W1, p_w1t, D_MODEL, D_FF);
    transpose_kernel<<<dim3(D_MODEL/32, D_FF/32),    t32x8>>>(W2, p_w2t, D_FF,    D_MODEL);

    // 1. nx = LN1(x)  (half)
    ln_kernel<<<MROWS, t256>>>(x, g1, b1, p_nx);

    // 2. Q/K/V (fused launch, head-permuted half outputs)
    dim3 gQKV(D_MODEL / BN, MROWS / BM, 3);
    tc_gemm_qkv<<<gQKV, t256, GEMM_SMEM>>>(p_nx, p_wqt, p_wkt, p_wvt,
                                           bq, bk, bv, p_q, p_k, p_v);

    // 3. causal flash attention (fp16 mma)
    dim3 gAttn(SEQ / 128, BATCH * NHEAD);
    attn_kernel<<<gAttn, t256>>>(p_q, p_k, p_v, p_attn);

    // 4. x1 = x + attn @ Wo + bo  (fp32 out)
    dim3 gD(D_MODEL / BN, MROWS / BM);
    tc_gemm<2><<<gD, t256, GEMM_SMEM>>>(p_attn, p_wot, bo, x, p_x1, D_MODEL, D_MODEL);

    // 5. nx2 = LN2(x1)  (half)
    ln_kernel<<<MROWS, t256>>>(p_x1, g2, b2, p_nx2);

    // 6. h = gelu(nx2 @ W1 + bf1)  (half out)
    dim3 gF1(D_FF / BN, MROWS / BM);
    tc_gemm<1><<<gF1, t256, GEMM_SMEM>>>(p_nx2, p_w1t, bf1, nullptr, p_ffh, D_FF, D_MODEL);

    // 7. out = x1 + h @ W2 + bf2  (fp32 out)
    tc_gemm<2><<<gD, t256, GEMM_SMEM>>>(p_ffh, p_w2t, bf2, p_x1, out, D_MODEL, D_FF);
}

// round 6
// speedup vs baseline: 5.4729x; 1.2384x over previous
#include <cuda_runtime.h>
#include <cuda_fp16.h>
#include <math.h>
#include <stdint.h>

#define D_MODEL 1024
#define NHEAD   16
#define HEAD_DIM 64
#define D_FF    4096
#define BATCH   2
#define SEQ     2048
#define MROWS   (BATCH * SEQ)   // 4096
#define LN_EPS  1e-5f

// ---------------------------------------------------------------------------
// Scratch (device globals)
// ---------------------------------------------------------------------------
__device__ __half g_nx  [MROWS * D_MODEL];
__device__ __half g_q   [MROWS * D_MODEL];   // [B*H, L, 64]
__device__ __half g_k   [MROWS * D_MODEL];
__device__ __half g_v   [MROWS * D_MODEL];
__device__ __half g_attn[MROWS * D_MODEL];   // [B, L, D]
__device__ float  g_x1  [MROWS * D_MODEL];
__device__ __half g_nx2 [MROWS * D_MODEL];
__device__ __half g_ffh [MROWS * D_FF];
__device__ __half g_wqt [D_MODEL * D_MODEL]; // [N][K]
__device__ __half g_wkt [D_MODEL * D_MODEL];
__device__ __half g_wvt [D_MODEL * D_MODEL];
__device__ __half g_wot [D_MODEL * D_MODEL];
__device__ __half g_w1t [D_MODEL * D_FF];
__device__ __half g_w2t [D_MODEL * D_FF];

// ---------------------------------------------------------------------------
// Helpers
// ---------------------------------------------------------------------------
__device__ __forceinline__ uint32_t smem_u32(const void* p) {
    uint32_t a;
    asm("{ .reg .u64 t; cvta.to.shared.u64 t, %1; cvt.u32.u64 %0, t; }" : "=r"(a) : "l"(p));
    return a;
}
__device__ __forceinline__ uint32_t pack_f2h2(float lo, float hi) {
    uint32_t r;
    asm("cvt.rn.f16x2.f32 %0, %1, %2;" : "=r"(r) : "f"(hi), "f"(lo));
    return r;
}
__device__ __forceinline__ float gelu_exact(float v) {
    return 0.5f * v * (1.0f + erff(v * 0.70710678118654752f));
}

#define CP_ASYNC(dst, src) \
    asm volatile("cp.async.cg.shared.global [%0], [%1], 16;" :: "r"(dst), "l"(src))
#define CP_COMMIT() asm volatile("cp.async.commit_group;")
#define CP_WAIT1()  asm volatile("cp.async.wait_group 1;")
#define CP_WAIT0()  asm volatile("cp.async.wait_group 0;")

#define LDSM4(r, addr) \
    asm volatile("ldmatrix.sync.aligned.m8n8.x4.shared.b16 {%0,%1,%2,%3}, [%4];" \
        : "=r"((r)[0]), "=r"((r)[1]), "=r"((r)[2]), "=r"((r)[3]) : "r"(addr))

__device__ __forceinline__ void mma_f16(float* c,
    uint32_t a0, uint32_t a1, uint32_t a2, uint32_t a3, uint32_t b0, uint32_t b1)
{
    asm volatile(
        "mma.sync.aligned.m16n8k16.row.col.f32.f16.f16.f32 "
        "{%0,%1,%2,%3}, {%4,%5,%6,%7}, {%8,%9}, {%0,%1,%2,%3};"
        : "+f"(c[0]), "+f"(c[1]), "+f"(c[2]), "+f"(c[3])
        : "r"(a0), "r"(a1), "r"(a2), "r"(a3), "r"(b0), "r"(b1));
}

// ---------------------------------------------------------------------------
// Weight transpose (fp32 [K][N] -> half [N][K]), 64x64 tiles, 16 elem/thread
// ---------------------------------------------------------------------------
__global__ void transpose_kernel(const float* __restrict__ in, __half* __restrict__ out,
                                 int K, int N)
{
    __shared__ float tile[64][65];
    int tid = threadIdx.x;
    int tx = tid & 63;
    int tg = tid >> 6;          // 0..3
    int x  = blockIdx.x * 64 + tx;   // N index
    int y0 = blockIdx.y * 64;        // K base
    #pragma unroll
    for (int i = 0; i < 16; i++) {
        int r = tg * 16 + i;
        tile[r][tx] = in[(size_t)(y0 + r) * N + x];
    }
    __syncthreads();
    int xo  = blockIdx.y * 64 + tx;  // K index
    int yo0 = blockIdx.x * 64;       // N base
    #pragma unroll
    for (int i = 0; i < 16; i++) {
        int r = tg * 16 + i;
        out[(size_t)(yo0 + r) * K + xo] = __float2half(tile[tx][r]);
    }
}

// ---------------------------------------------------------------------------
// LayerNorm: fp32 in, half out
// ---------------------------------------------------------------------------
__global__ void ln_kernel(const float* __restrict__ x, const float* __restrict__ g,
                          const float* __restrict__ b, __half* __restrict__ out)
{
    int row = blockIdx.x;
    int tid = threadIdx.x;
    const float* xr = x + (size_t)row * D_MODEL;
    int c = tid * 4;
    float4 v = *(const float4*)(xr + c);

    float s  = v.x + v.y + v.z + v.w;
    float ss = v.x*v.x + v.y*v.y + v.z*v.z + v.w*v.w;
    #pragma unroll
    for (int o = 16; o > 0; o >>= 1) {
        s  += __shfl_xor_sync(0xffffffffu, s,  o);
        ss += __shfl_xor_sync(0xffffffffu, ss, o);
    }
    __shared__ float smS[8], smSS[8];
    int w = tid >> 5, lane = tid & 31;
    if (lane == 0) { smS[w] = s; smSS[w] = ss; }
    __syncthreads();
    float tot = 0.f, tot2 = 0.f;
    #pragma unroll
    for (int i = 0; i < 8; i++) { tot += smS[i]; tot2 += smSS[i]; }

    float mu   = tot  * (1.0f / D_MODEL);
    float var  = tot2 * (1.0f / D_MODEL) - mu * mu;
    float rstd = rsqrtf(var + LN_EPS);

    float4 gv = *(const float4*)(g + c);
    float4 bv = *(const float4*)(b + c);
    __half2* o2 = (__half2*)(out + (size_t)row * D_MODEL + c);
    o2[0] = __floats2half2_rn((v.x - mu) * rstd * gv.x + bv.x,
                              (v.y - mu) * rstd * gv.y + bv.y);
    o2[1] = __floats2half2_rn((v.z - mu) * rstd * gv.z + bv.z,
                              (v.w - mu) * rstd * gv.w + bv.w);
}

// ---------------------------------------------------------------------------
// fp16 mma GEMM: C[M,N] = A[M,K] @ WT[N,K]^T  — ldmatrix + 3-stage cp.async
// BM=BN=128, BK=32 halves, 256 thr (8 warps 2x4), warp 64x32, m16n8k16.
// ---------------------------------------------------------------------------
#define BM 128
#define BN 128
#define BKh 32
#define LDH 40                        // halves per smem row (32 + 8 pad)
#define ASZH (BM * LDH)               // halves per A tile (=B tile)
#define ASZB (ASZH * 2)               // bytes
#define STAGEB (2 * ASZB)             // bytes per stage (A+B) = 20480
#define GEMM_SMEM (3 * STAGEB)        // 61440

struct Frag { float c[4][4][4]; };

__device__ __forceinline__ void mma_mainloop(const __half* __restrict__ A,
                                             const __half* __restrict__ WT,
                                             int K, int row0, int col0,
                                             __half* sm, Frag& F)
{
    int tid  = threadIdx.x;
    int lane = tid & 31, wid = tid >> 5;
    int wm = wid >> 2, wn = wid & 3;
    int rr = lane & 7, mat = lane >> 3;

    uint32_t sbase = smem_u32(sm);

    // cp.async loader geometry: 16B chunk; r = tid>>2 (+64), c8 = tid&3
    int r0 = tid >> 2;
    int c8 = tid & 3;
    const __half* gA = A  + (size_t)(row0 + r0) * K + c8 * 8;
    const __half* gB = WT + (size_t)(col0 + r0) * K + c8 * 8;
    uint32_t stA0 = (uint32_t)((r0)      * LDH + c8 * 8) * 2;
    uint32_t stA1 = (uint32_t)((r0 + 64) * LDH + c8 * 8) * 2;
    uint32_t stB0 = stA0 + ASZB;
    uint32_t stB1 = stA1 + ASZB;

    // ldmatrix per-lane byte offsets (within a stage)
    // A x4 at (mf, ks): mats {m..m+7,k}, {m+8..,k}, {m..,k+8}, {m+8..,k+8}
    uint32_t offA[2][4], offB[2][2];
    #pragma unroll
    for (int ks = 0; ks < 2; ks++) {
        #pragma unroll
        for (int mf = 0; mf < 4; mf++) {
            int row = wm * 64 + mf * 16 + rr + ((mat & 1) ? 8 : 0);
            int col = ks * 16 + ((mat & 2) ? 8 : 0);
            offA[ks][mf] = (uint32_t)(row * LDH + col) * 2;
        }
        #pragma unroll
        for (int pr = 0; pr < 2; pr++) {
            // B x4: mats {n..n+7,k}, {n..,k+8}, {n+8..,k}, {n+8..,k+8}
            int row = wn * 32 + pr * 16 + rr + ((mat & 2) ? 8 : 0);
            int col = ks * 16 + ((mat & 1) ? 8 : 0);
            offB[ks][pr] = (uint32_t)(row * LDH + col) * 2 + ASZB;
        }
    }

    #pragma unroll
    for (int mf = 0; mf < 4; mf++)
        #pragma unroll
        for (int nf = 0; nf < 4; nf++)
            #pragma unroll
            for (int r = 0; r < 4; r++) F.c[mf][nf][r] = 0.f;

    int nk = K / BKh;

    // prologue: stages 0 and 1
    #pragma unroll
    for (int s = 0; s < 2; s++) {
        uint32_t sb = sbase + s * STAGEB;
        CP_ASYNC(sb + stA0, gA + (size_t)s * BKh);
        CP_ASYNC(sb + stA1, gA + (size_t)64 * K + (size_t)s * BKh);
        CP_ASYNC(sb + stB0, gB + (size_t)s * BKh);
        CP_ASYNC(sb + stB1, gB + (size_t)64 * K + (size_t)s * BKh);
        CP_COMMIT();
    }

    for (int kt = 0; kt < nk; kt++) {
        if (kt == nk - 1) { CP_WAIT0(); } else { CP_WAIT1(); }
        __syncthreads();

        // refill stage (kt+2)%3 — safe: it was read in iter kt-1, barrier passed
        if (kt + 2 < nk) {
            uint32_t sb = sbase + ((kt + 2) % 3) * STAGEB;
            const __half* a = gA + (size_t)(kt + 2) * BKh;
            const __half* b = gB + (size_t)(kt + 2) * BKh;
            CP_ASYNC(sb + stA0, a);
            CP_ASYNC(sb + stA1, a + (size_t)64 * K);
            CP_ASYNC(sb + stB0, b);
            CP_ASYNC(sb + stB1, b + (size_t)64 * K);
            CP_COMMIT();
        }

        uint32_t sb = sbase + (kt % 3) * STAGEB;
        #pragma unroll
        for (int ks = 0; ks < 2; ks++) {
            uint32_t bb0[4], bb1[4];
            LDSM4(bb0, sb + offB[ks][0]);
            LDSM4(bb1, sb + offB[ks][1]);
            #pragma unroll
            for (int mf = 0; mf < 4; mf++) {
                uint32_t aa[4];
                LDSM4(aa, sb + offA[ks][mf]);
                mma_f16(F.c[mf][0], aa[0], aa[1], aa[2], aa[3], bb0[0], bb0[1]);
                mma_f16(F.c[mf][1], aa[0], aa[1], aa[2], aa[3], bb0[2], bb0[3]);
                mma_f16(F.c[mf][2], aa[0], aa[1], aa[2], aa[3], bb1[0], bb1[1]);
                mma_f16(F.c[mf][3], aa[0], aa[1], aa[2], aa[3], bb1[2], bb1[3]);
            }
        }
    }
}

// QKV: gridDim.z selects weight; writes head-permuted half [B*H, L, 64]
__global__ __launch_bounds__(256, 2)
void tc_gemm_qkv(const __half* __restrict__ A,
                 const __half* __restrict__ Wqt, const __half* __restrict__ Wkt,
                 const __half* __restrict__ Wvt,
                 const float* __restrict__ bq, const float* __restrict__ bk,
                 const float* __restrict__ bv,
                 __half* __restrict__ Cq, __half* __restrict__ Ck, __half* __restrict__ Cv)
{
    extern __shared__ __half sm[];
    int z = blockIdx.z;
    const __half* WT  = (z == 0) ? Wqt : (z == 1) ? Wkt : Wvt;
    const float* bias = (z == 0) ? bq  : (z == 1) ? bk  : bv;
    __half* C         = (z == 0) ? Cq  : (z == 1) ? Ck  : Cv;

    int row0 = blockIdx.y * BM;
    int col0 = blockIdx.x * BN;
    Frag F;
    mma_mainloop(A, WT, D_MODEL, row0, col0, sm, F);

    int lane = threadIdx.x & 31, wid = threadIdx.x >> 5;
    int wm = wid >> 2, wn = wid & 3;
    int group = lane >> 2, tig = lane & 3;

    #pragma unroll
    for (int mf = 0; mf < 4; mf++) {
        #pragma unroll
        for (int nf = 0; nf < 4; nf++) {
            int row = row0 + wm * 64 + mf * 16 + group;
            int col = col0 + wn * 32 + nf * 8 + 2 * tig;
            float2 bv2 = *(const float2*)(bias + col);
            int h = col >> 6, d = col & 63;
            #pragma unroll
            for (int hi = 0; hi < 2; hi++) {
                int r = row + hi * 8;
                int b = r >> 11, l = r & (SEQ - 1);
                __half2 o = __floats2half2_rn(F.c[mf][nf][hi * 2 + 0] + bv2.x,
                                              F.c[mf][nf][hi * 2 + 1] + bv2.y);
                *(__half2*)(C + (((size_t)(b * NHEAD + h) * SEQ) + l) * HEAD_DIM + d) = o;
            }
        }
    }
}

// MODE 1: half out = gelu(acc+bias).  MODE 2: float out = res + acc + bias.
template<int MODE>
__global__ __launch_bounds__(256, 2)
void tc_gemm(const __half* __restrict__ A, const __half* __restrict__ WT,
             const float* __restrict__ bias, const float* __restrict__ res,
             void* __restrict__ Cv, int N, int K)
{
    extern __shared__ __half sm[];
    int row0 = blockIdx.y * BM;
    int col0 = blockIdx.x * BN;
    Frag F;
    mma_mainloop(A, WT, K, row0, col0, sm, F);

    int lane = threadIdx.x & 31, wid = threadIdx.x >> 5;
    int wm = wid >> 2, wn = wid & 3;
    int group = lane >> 2, tig = lane & 3;

    #pragma unroll
    for (int mf = 0; mf < 4; mf++) {
        #pragma unroll
        for (int nf = 0; nf < 4; nf++) {
            int row = row0 + wm * 64 + mf * 16 + group;
            int col = col0 + wn * 32 + nf * 8 + 2 * tig;
            float2 bv2 = *(const float2*)(bias + col);
            #pragma unroll
            for (int hi = 0; hi < 2; hi++) {
                int r = row + hi * 8;
                float ox = F.c[mf][nf][hi * 2 + 0] + bv2.x;
                float oy = F.c[mf][nf][hi * 2 + 1] + bv2.y;
                if (MODE == 1) {
                    __half2 o = __floats2half2_rn(gelu_exact(ox), gelu_exact(oy));
                    *(__half2*)((__half*)Cv + (size_t)r * N + col) = o;
                } else {
                    float2 r2 = *(const float2*)(res + (size_t)r * N + col);
                    float2 o; o.x = ox + r2.x; o.y = oy + r2.y;
                    *(float2*)((float*)Cv + (size_t)r * N + col) = o;
                }
            }
        }
    }
}

// ---------------------------------------------------------------------------
// fp16 mma flash attention (causal). 128 q rows/block, 8 warps, 64-key tiles.
// ---------------------------------------------------------------------------
__global__ __launch_bounds__(256)
void attn_kernel(const __half* __restrict__ Q, const __half* __restrict__ K,
                 const __half* __restrict__ V, __half* __restrict__ out)
{
    __shared__ __half Qs[128][72];
    __shared__ __half Ks[64][72];
    __shared__ __half Vt[64][72];   // transposed: [d][key]

    int tid = threadIdx.x;
    int lane = tid & 31, wid = tid >> 5;
    int group = lane >> 2, tig = lane & 3;
    int qb = blockIdx.x * 128;
    int bh = blockIdx.y;
    int wb = wid * 16;

    const __half* Qb = Q + (size_t)bh * SEQ * HEAD_DIM;
    const __half* Kb = K + (size_t)bh * SEQ * HEAD_DIM;
    const __half* Vb = V + (size_t)bh * SEQ * HEAD_DIM;

    #pragma unroll
    for (int i = 0; i < 4; i++) {
        int e = tid + i * 256;
        int r = e >> 3, c = e & 7;
        *(uint4*)&Qs[r][c * 8] = *(const uint4*)(Qb + (size_t)(qb + r) * HEAD_DIM + c * 8);
    }
    __syncthreads();

    uint32_t qa[4][4];
    #pragma unroll
    for (int ks = 0; ks < 4; ks++) {
        int kb = ks * 16 + 2 * tig;
        qa[ks][0] = *(const uint32_t*)&Qs[wb + group][kb];
        qa[ks][1] = *(const uint32_t*)&Qs[wb + group + 8][kb];
        qa[ks][2] = *(const uint32_t*)&Qs[wb + group][kb + 8];
        qa[ks][3] = *(const uint32_t*)&Qs[wb + group + 8][kb + 8];
    }

    float o[8][4];
    #pragma unroll
    for (int i = 0; i < 8; i++)
        #pragma unroll
        for (int j = 0; j < 4; j++) o[i][j] = 0.f;
    float m2[2] = {-1e30f, -1e30f};
    float l2[2] = {0.f, 0.f};

    const float scale = 0.125f;
    int row_g0 = qb + wb + group;
    int nkt = (qb >> 6) + 2;

    for (int kt = 0; kt < nkt; kt++) {
        __syncthreads();
        #pragma unroll
        for (int i = 0; i < 2; i++) {
            int e = tid + i * 256;
            int r = e >> 3, c = e & 7;
            *(uint4*)&Ks[r][c * 8] = *(const uint4*)(Kb + (size_t)(kt * 64 + r) * HEAD_DIM + c * 8);
        }
        #pragma unroll
        for (int i = 0; i < 8; i++) {
            int e = tid + i * 256;
            int key = e >> 5, c = e & 31;
            __half2 v2 = *(const __half2*)(Vb + (size_t)(kt * 64 + key) * HEAD_DIM + 2 * c);
            Vt[2 * c][key]     = __low2half(v2);
            Vt[2 * c + 1][key] = __high2half(v2);
        }
        __syncthreads();

        bool active = (kt * 64) <= (qb + wb + 15);
        if (active) {
            float s[8][4];
            #pragma unroll
            for (int nf = 0; nf < 8; nf++)
                #pragma unroll
                for (int c = 0; c < 4; c++) s[nf][c] = 0.f;
            #pragma unroll
            for (int ks = 0; ks < 4; ks++) {
                int kb = ks * 16 + 2 * tig;
                #pragma unroll
                for (int nf = 0; nf < 8; nf++) {
                    uint32_t b0 = *(const uint32_t*)&Ks[nf * 8 + group][kb];
                    uint32_t b1 = *(const uint32_t*)&Ks[nf * 8 + group][kb + 8];
                    mma_f16(s[nf], qa[ks][0], qa[ks][1], qa[ks][2], qa[ks][3], b0, b1);
                }
            }

            bool need_mask = (kt * 64 + 63) > (qb + wb);
            #pragma unroll
            for (int nf = 0; nf < 8; nf++) {
                #pragma unroll
                for (int c = 0; c < 4; c++) {
                    float v = s[nf][c] * scale;
                    if (need_mask) {
                        int key = kt * 64 + nf * 8 + 2 * tig + (c & 1);
                        int rg  = row_g0 + ((c >= 2) ? 8 : 0);
                        if (key > rg) v = -1e30f;
                    }
                    s[nf][c] = v;
                }
            }

            #pragma unroll
            for (int r = 0; r < 2; r++) {
                float mx = -1e30f;
                #pragma unroll
                for (int nf = 0; nf < 8; nf++)
                    mx = fmaxf(mx, fmaxf(s[nf][2 * r], s[nf][2 * r + 1]));
                mx = fmaxf(mx, __shfl_xor_sync(0xffffffffu, mx, 1));
                mx = fmaxf(mx, __shfl_xor_sync(0xffffffffu, mx, 2));
                float mnew = fmaxf(m2[r], mx);
                float corr = __expf(m2[r] - mnew);
                float rsum = 0.f;
                #pragma unroll
                for (int nf = 0; nf < 8; nf++) {
                    float p0 = __expf(s[nf][2 * r]     - mnew);
                    float p1 = __expf(s[nf][2 * r + 1] - mnew);
                    s[nf][2 * r] = p0; s[nf][2 * r + 1] = p1;
                    rsum += p0 + p1;
                }
                rsum += __shfl_xor_sync(0xffffffffu, rsum, 1);
                rsum += __shfl_xor_sync(0xffffffffu, rsum, 2);
                l2[r] = l2[r] * corr + rsum;
                m2[r] = mnew;
                #pragma unroll
                for (int nfd = 0; nfd < 8; nfd++) {
                    o[nfd][2 * r]     *= corr;
                    o[nfd][2 * r + 1] *= corr;
                }
            }

            #pragma unroll
            for (int ks = 0; ks < 4; ks++) {
                uint32_t pa0 = pack_f2h2(s[2*ks][0],   s[2*ks][1]);
                uint32_t pa1 = pack_f2h2(s[2*ks][2],   s[2*ks][3]);
                uint32_t pa2 = pack_f2h2(s[2*ks+1][0], s[2*ks+1][1]);
                uint32_t pa3 = pack_f2h2(s[2*ks+1][2], s[2*ks+1][3]);
                int kb = ks * 16 + 2 * tig;
                #pragma unroll
                for (int nfd = 0; nfd < 8; nfd++) {
                    uint32_t b0 = *(const uint32_t*)&Vt[nfd * 8 + group][kb];
                    uint32_t b1 = *(const uint32_t*)&Vt[nfd * 8 + group][kb + 8];
                    mma_f16(o[nfd], pa0, pa1, pa2, pa3, b0, b1);
                }
            }
        }
    }

    int b = bh >> 4, h = bh & 15;
    float inv0 = 1.0f / l2[0];
    float inv1 = 1.0f / l2[1];
    #pragma unroll
    for (int r = 0; r < 2; r++) {
        int rg = row_g0 + r * 8;
        int l = rg & (SEQ - 1);
        float inv = r ? inv1 : inv0;
        #pragma unroll
        for (int nfd = 0; nfd < 8; nfd++) {
            int d = nfd * 8 + 2 * tig;
            __half2 ov = __floats2half2_rn(o[nfd][2 * r] * inv, o[nfd][2 * r + 1] * inv);
            *(__half2*)(out + ((size_t)(b * SEQ + l)) * D_MODEL + h * HEAD_DIM + d) = ov;
        }
    }
}

// ---------------------------------------------------------------------------
// Launch
// ---------------------------------------------------------------------------
extern "C" void kernel_launch(void* const* d_in, const int* in_sizes, int n_in,
                              void* d_out, int out_size)
{
    const float* x   = (const float*)d_in[0];
    const float* Wq  = (const float*)d_in[2];
    const float* bq  = (const float*)d_in[3];
    const float* Wk  = (const float*)d_in[4];
    const float* bk  = (const float*)d_in[5];
    const float* Wv  = (const float*)d_in[6];
    const float* bv  = (const float*)d_in[7];
    const float* Wo  = (const float*)d_in[8];
    const float* bo  = (const float*)d_in[9];
    const float* g1  = (const float*)d_in[10];
    const float* b1  = (const float*)d_in[11];
    const float* g2  = (const float*)d_in[12];
    const float* b2  = (const float*)d_in[13];
    const float* W1  = (const float*)d_in[14];
    const float* bf1 = (const float*)d_in[15];
    const float* W2  = (const float*)d_in[16];
    const float* bf2 = (const float*)d_in[17];
    float* out = (float*)d_out;

    __half *p_nx, *p_q, *p_k, *p_v, *p_attn, *p_nx2, *p_ffh;
    __half *p_wqt, *p_wkt, *p_wvt, *p_wot, *p_w1t, *p_w2t;
    float *p_x1;
    cudaGetSymbolAddress((void**)&p_nx,   g_nx);
    cudaGetSymbolAddress((void**)&p_q,    g_q);
    cudaGetSymbolAddress((void**)&p_k,    g_k);
    cudaGetSymbolAddress((void**)&p_v,    g_v);
    cudaGetSymbolAddress((void**)&p_attn, g_attn);
    cudaGetSymbolAddress((void**)&p_x1,   g_x1);
    cudaGetSymbolAddress((void**)&p_nx2,  g_nx2);
    cudaGetSymbolAddress((void**)&p_ffh,  g_ffh);
    cudaGetSymbolAddress((void**)&p_wqt,  g_wqt);
    cudaGetSymbolAddress((void**)&p_wkt,  g_wkt);
    cudaGetSymbolAddress((void**)&p_wvt,  g_wvt);
    cudaGetSymbolAddress((void**)&p_wot,  g_wot);
    cudaGetSymbolAddress((void**)&p_w1t,  g_w1t);
    cudaGetSymbolAddress((void**)&p_w2t,  g_w2t);

    cudaFuncSetAttribute(tc_gemm_qkv, cudaFuncAttributeMaxDynamicSharedMemorySize, GEMM_SMEM);
    cudaFuncSetAttribute(tc_gemm<1>,  cudaFuncAttributeMaxDynamicSharedMemorySize, GEMM_SMEM);
    cudaFuncSetAttribute(tc_gemm<2>,  cudaFuncAttributeMaxDynamicSharedMemorySize, GEMM_SMEM);

    dim3 t256(256);

    // 0. transpose weights to [N][K] half
    transpose_kernel<<<dim3(D_MODEL/64, D_MODEL/64), t256>>>(Wq, p_wqt, D_MODEL, D_MODEL);
    transpose_kernel<<<dim3(D_MODEL/64, D_MODEL/64), t256>>>(Wk, p_wkt, D_MODEL, D_MODEL);
    transpose_kernel<<<dim3(D_MODEL/64, D_MODEL/64), t256>>>(Wv, p_wvt, D_MODEL, D_MODEL);
    transpose_kernel<<<dim3(D_MODEL/64, D_MODEL/64), t256>>>(Wo, p_wot, D_MODEL, D_MODEL);
    transpose_kernel<<<dim3(D_FF/64,    D_MODEL/64), t256>>>(W1, p_w1t, D_MODEL, D_FF);
    transpose_kernel<<<dim3(D_MODEL/64, D_FF/64),    t256>>>(W2, p_w2t, D_FF,    D_MODEL);

    // 1. nx = LN1(x)
    ln_kernel<<<MROWS, t256>>>(x, g1, b1, p_nx);

    // 2. Q/K/V (fused launch)
    dim3 gQKV(D_MODEL / BN, MROWS / BM, 3);
    tc_gemm_qkv<<<gQKV, t256, GEMM_SMEM>>>(p_nx, p_wqt, p_wkt, p_wvt,
                                           bq, bk, bv, p_q, p_k, p_v);

    // 3. causal flash attention
    dim3 gAttn(SEQ / 128, BATCH * NHEAD);
    attn_kernel<<<gAttn, t256>>>(p_q, p_k, p_v, p_attn);

    // 4. x1 = x + attn @ Wo + bo
    dim3 gD(D_MODEL / BN, MROWS / BM);
    tc_gemm<2><<<gD, t256, GEMM_SMEM>>>(p_attn, p_wot, bo, x, p_x1, D_MODEL, D_MODEL);

    // 5. nx2 = LN2(x1)
    ln_kernel<<<MROWS, t256>>>(p_x1, g2, b2, p_nx2);

    // 6. h = gelu(nx2 @ W1 + bf1)
    dim3 gF1(D_FF / BN, MROWS / BM);
    tc_gemm<1><<<gF1, t256, GEMM_SMEM>>>(p_nx2, p_w1t, bf1, nullptr, p_ffh, D_FF, D_MODEL);

    // 7. out = x1 + h @ W2 + bf2
    tc_gemm<2><<<gD, t256, GEMM_SMEM>>>(p_ffh, p_w2t, bf2, p_x1, out, D_MODEL, D_FF);
}

// round 7
// speedup vs baseline: 6.1407x; 1.1220x over previous
#include <cuda_runtime.h>
#include <cuda_fp16.h>
#include <math.h>
#include <stdint.h>

#define D_MODEL 1024
#define NHEAD   16
#define HEAD_DIM 64
#define D_FF    4096
#define BATCH   2
#define SEQ     2048
#define MROWS   (BATCH * SEQ)   // 4096
#define LN_EPS  1e-5f

// ---------------------------------------------------------------------------
// Scratch (device globals)
// ---------------------------------------------------------------------------
__device__ __half g_nx  [MROWS * D_MODEL];
__device__ __half g_q   [MROWS * D_MODEL];   // [B*H, L, 64]
__device__ __half g_k   [MROWS * D_MODEL];
__device__ __half g_v   [MROWS * D_MODEL];
__device__ __half g_attn[MROWS * D_MODEL];   // [B, L, D]
__device__ float  g_x1  [MROWS * D_MODEL];
__device__ __half g_nx2 [MROWS * D_MODEL];
__device__ __half g_ffh [MROWS * D_FF];
__device__ __half g_wqt [D_MODEL * D_MODEL]; // [N][K]
__device__ __half g_wkt [D_MODEL * D_MODEL];
__device__ __half g_wvt [D_MODEL * D_MODEL];
__device__ __half g_wot [D_MODEL * D_MODEL];
__device__ __half g_w1t [D_MODEL * D_FF];
__device__ __half g_w2t [D_MODEL * D_FF];

// ---------------------------------------------------------------------------
// Helpers
// ---------------------------------------------------------------------------
__device__ __forceinline__ uint32_t smem_u32(const void* p) {
    uint32_t a;
    asm("{ .reg .u64 t; cvta.to.shared.u64 t, %1; cvt.u32.u64 %0, t; }" : "=r"(a) : "l"(p));
    return a;
}
__device__ __forceinline__ uint32_t pack_f2h2(float lo, float hi) {
    uint32_t r;
    asm("cvt.rn.f16x2.f32 %0, %1, %2;" : "=r"(r) : "f"(hi), "f"(lo));
    return r;
}
__device__ __forceinline__ float gelu_exact(float v) {
    return 0.5f * v * (1.0f + erff(v * 0.70710678118654752f));
}

#define CP_ASYNC(dst, src) \
    asm volatile("cp.async.cg.shared.global [%0], [%1], 16;" :: "r"(dst), "l"(src))
#define CP_COMMIT() asm volatile("cp.async.commit_group;")
#define CP_WAIT1()  asm volatile("cp.async.wait_group 1;")
#define CP_WAIT0()  asm volatile("cp.async.wait_group 0;")

#define LDSM4(r, addr) \
    asm volatile("ldmatrix.sync.aligned.m8n8.x4.shared.b16 {%0,%1,%2,%3}, [%4];" \
        : "=r"((r)[0]), "=r"((r)[1]), "=r"((r)[2]), "=r"((r)[3]) : "r"(addr))
#define LDSM4T(r, addr) \
    asm volatile("ldmatrix.sync.aligned.m8n8.x4.trans.shared.b16 {%0,%1,%2,%3}, [%4];" \
        : "=r"((r)[0]), "=r"((r)[1]), "=r"((r)[2]), "=r"((r)[3]) : "r"(addr))

__device__ __forceinline__ void mma_f16(float* c,
    uint32_t a0, uint32_t a1, uint32_t a2, uint32_t a3, uint32_t b0, uint32_t b1)
{
    asm volatile(
        "mma.sync.aligned.m16n8k16.row.col.f32.f16.f16.f32 "
        "{%0,%1,%2,%3}, {%4,%5,%6,%7}, {%8,%9}, {%0,%1,%2,%3};"
        : "+f"(c[0]), "+f"(c[1]), "+f"(c[2]), "+f"(c[3])
        : "r"(a0), "r"(a1), "r"(a2), "r"(a3), "r"(b0), "r"(b1));
}

// ---------------------------------------------------------------------------
// Weight transpose (fp32 [K][N] -> half [N][K]) — generic + batched-x4 square
// ---------------------------------------------------------------------------
__device__ __forceinline__ void transpose_body(const float* __restrict__ in,
                                               __half* __restrict__ out, int K, int N)
{
    __shared__ float tile[64][65];
    int tid = threadIdx.x;
    int tx = tid & 63;
    int tg = tid >> 6;
    int x  = blockIdx.x * 64 + tx;
    int y0 = blockIdx.y * 64;
    #pragma unroll
    for (int i = 0; i < 16; i++) {
        int r = tg * 16 + i;
        tile[r][tx] = in[(size_t)(y0 + r) * N + x];
    }
    __syncthreads();
    int xo  = blockIdx.y * 64 + tx;
    int yo0 = blockIdx.x * 64;
    #pragma unroll
    for (int i = 0; i < 16; i++) {
        int r = tg * 16 + i;
        out[(size_t)(yo0 + r) * K + xo] = __float2half(tile[tx][r]);
    }
}

__global__ void transpose_kernel(const float* __restrict__ in, __half* __restrict__ out,
                                 int K, int N)
{
    transpose_body(in, out, K, N);
}

__global__ void transpose4_kernel(const float* __restrict__ w0, const float* __restrict__ w1,
                                  const float* __restrict__ w2, const float* __restrict__ w3,
                                  __half* __restrict__ o0, __half* __restrict__ o1,
                                  __half* __restrict__ o2, __half* __restrict__ o3)
{
    int z = blockIdx.z;
    const float* in = (z == 0) ? w0 : (z == 1) ? w1 : (z == 2) ? w2 : w3;
    __half* out     = (z == 0) ? o0 : (z == 1) ? o1 : (z == 2) ? o2 : o3;
    transpose_body(in, out, D_MODEL, D_MODEL);
}

// ---------------------------------------------------------------------------
// LayerNorm: fp32 in, half out
// ---------------------------------------------------------------------------
__global__ void ln_kernel(const float* __restrict__ x, const float* __restrict__ g,
                          const float* __restrict__ b, __half* __restrict__ out)
{
    int row = blockIdx.x;
    int tid = threadIdx.x;
    const float* xr = x + (size_t)row * D_MODEL;
    int c = tid * 4;
    float4 v = *(const float4*)(xr + c);

    float s  = v.x + v.y + v.z + v.w;
    float ss = v.x*v.x + v.y*v.y + v.z*v.z + v.w*v.w;
    #pragma unroll
    for (int o = 16; o > 0; o >>= 1) {
        s  += __shfl_xor_sync(0xffffffffu, s,  o);
        ss += __shfl_xor_sync(0xffffffffu, ss, o);
    }
    __shared__ float smS[8], smSS[8];
    int w = tid >> 5, lane = tid & 31;
    if (lane == 0) { smS[w] = s; smSS[w] = ss; }
    __syncthreads();
    float tot = 0.f, tot2 = 0.f;
    #pragma unroll
    for (int i = 0; i < 8; i++) { tot += smS[i]; tot2 += smSS[i]; }

    float mu   = tot  * (1.0f / D_MODEL);
    float var  = tot2 * (1.0f / D_MODEL) - mu * mu;
    float rstd = rsqrtf(var + LN_EPS);

    float4 gv = *(const float4*)(g + c);
    float4 bv = *(const float4*)(b + c);
    __half2* o2 = (__half2*)(out + (size_t)row * D_MODEL + c);
    o2[0] = __floats2half2_rn((v.x - mu) * rstd * gv.x + bv.x,
                              (v.y - mu) * rstd * gv.y + bv.y);
    o2[1] = __floats2half2_rn((v.z - mu) * rstd * gv.z + bv.z,
                              (v.w - mu) * rstd * gv.w + bv.w);
}

// ---------------------------------------------------------------------------
// fp16 mma GEMM: C[M,N] = A[M,K] @ WT[N,K]^T  — ldmatrix + 3-stage cp.async
// ---------------------------------------------------------------------------
#define BM 128
#define BN 128
#define BKh 32
#define LDH 40
#define ASZH (BM * LDH)
#define ASZB (ASZH * 2)
#define STAGEB (2 * ASZB)             // 20480
#define GEMM_SMEM (3 * STAGEB)        // 61440

struct Frag { float c[4][4][4]; };

__device__ __forceinline__ void mma_mainloop(const __half* __restrict__ A,
                                             const __half* __restrict__ WT,
                                             int K, int row0, int col0,
                                             __half* sm, Frag& F)
{
    int tid  = threadIdx.x;
    int lane = tid & 31, wid = tid >> 5;
    int wm = wid >> 2, wn = wid & 3;
    int rr = lane & 7, mat = lane >> 3;

    uint32_t sbase = smem_u32(sm);

    int r0 = tid >> 2;
    int c8 = tid & 3;
    const __half* gA = A  + (size_t)(row0 + r0) * K + c8 * 8;
    const __half* gB = WT + (size_t)(col0 + r0) * K + c8 * 8;
    uint32_t stA0 = (uint32_t)((r0)      * LDH + c8 * 8) * 2;
    uint32_t stA1 = (uint32_t)((r0 + 64) * LDH + c8 * 8) * 2;
    uint32_t stB0 = stA0 + ASZB;
    uint32_t stB1 = stA1 + ASZB;

    uint32_t offA[2][4], offB[2][2];
    #pragma unroll
    for (int ks = 0; ks < 2; ks++) {
        #pragma unroll
        for (int mf = 0; mf < 4; mf++) {
            int row = wm * 64 + mf * 16 + rr + ((mat & 1) ? 8 : 0);
            int col = ks * 16 + ((mat & 2) ? 8 : 0);
            offA[ks][mf] = (uint32_t)(row * LDH + col) * 2;
        }
        #pragma unroll
        for (int pr = 0; pr < 2; pr++) {
            int row = wn * 32 + pr * 16 + rr + ((mat & 2) ? 8 : 0);
            int col = ks * 16 + ((mat & 1) ? 8 : 0);
            offB[ks][pr] = (uint32_t)(row * LDH + col) * 2 + ASZB;
        }
    }

    #pragma unroll
    for (int mf = 0; mf < 4; mf++)
        #pragma unroll
        for (int nf = 0; nf < 4; nf++)
            #pragma unroll
            for (int r = 0; r < 4; r++) F.c[mf][nf][r] = 0.f;

    int nk = K / BKh;

    #pragma unroll
    for (int s = 0; s < 2; s++) {
        uint32_t sb = sbase + s * STAGEB;
        CP_ASYNC(sb + stA0, gA + (size_t)s * BKh);
        CP_ASYNC(sb + stA1, gA + (size_t)64 * K + (size_t)s * BKh);
        CP_ASYNC(sb + stB0, gB + (size_t)s * BKh);
        CP_ASYNC(sb + stB1, gB + (size_t)64 * K + (size_t)s * BKh);
        CP_COMMIT();
    }

    uint32_t rdoff = 0, wroff = 2 * STAGEB;
    for (int kt = 0; kt < nk; kt++) {
        if (kt == nk - 1) { CP_WAIT0(); } else { CP_WAIT1(); }
        __syncthreads();

        if (kt + 2 < nk) {
            uint32_t sb = sbase + wroff;
            const __half* a = gA + (size_t)(kt + 2) * BKh;
            const __half* b = gB + (size_t)(kt + 2) * BKh;
            CP_ASYNC(sb + stA0, a);
            CP_ASYNC(sb + stA1, a + (size_t)64 * K);
            CP_ASYNC(sb + stB0, b);
            CP_ASYNC(sb + stB1, b + (size_t)64 * K);
            CP_COMMIT();
            wroff += STAGEB; if (wroff == 3 * STAGEB) wroff = 0;
        }

        uint32_t sb = sbase + rdoff;
        rdoff += STAGEB; if (rdoff == 3 * STAGEB) rdoff = 0;
        #pragma unroll
        for (int ks = 0; ks < 2; ks++) {
            uint32_t bb0[4], bb1[4];
            LDSM4(bb0, sb + offB[ks][0]);
            LDSM4(bb1, sb + offB[ks][1]);
            #pragma unroll
            for (int mf = 0; mf < 4; mf++) {
                uint32_t aa[4];
                LDSM4(aa, sb + offA[ks][mf]);
                mma_f16(F.c[mf][0], aa[0], aa[1], aa[2], aa[3], bb0[0], bb0[1]);
                mma_f16(F.c[mf][1], aa[0], aa[1], aa[2], aa[3], bb0[2], bb0[3]);
                mma_f16(F.c[mf][2], aa[0], aa[1], aa[2], aa[3], bb1[0], bb1[1]);
                mma_f16(F.c[mf][3], aa[0], aa[1], aa[2], aa[3], bb1[2], bb1[3]);
            }
        }
    }
}

// QKV: gridDim.z selects weight; writes head-permuted half [B*H, L, 64]
__global__ __launch_bounds__(256, 2)
void tc_gemm_qkv(const __half* __restrict__ A,
                 const __half* __restrict__ Wqt, const __half* __restrict__ Wkt,
                 const __half* __restrict__ Wvt,
                 const float* __restrict__ bq, const float* __restrict__ bk,
                 const float* __restrict__ bv,
                 __half* __restrict__ Cq, __half* __restrict__ Ck, __half* __restrict__ Cv)
{
    extern __shared__ __half sm[];
    int z = blockIdx.z;
    const __half* WT  = (z == 0) ? Wqt : (z == 1) ? Wkt : Wvt;
    const float* bias = (z == 0) ? bq  : (z == 1) ? bk  : bv;
    __half* C         = (z == 0) ? Cq  : (z == 1) ? Ck  : Cv;

    int row0 = blockIdx.y * BM;
    int col0 = blockIdx.x * BN;
    Frag F;
    mma_mainloop(A, WT, D_MODEL, row0, col0, sm, F);

    int lane = threadIdx.x & 31, wid = threadIdx.x >> 5;
    int wm = wid >> 2, wn = wid & 3;
    int group = lane >> 2, tig = lane & 3;

    #pragma unroll
    for (int mf = 0; mf < 4; mf++) {
        #pragma unroll
        for (int nf = 0; nf < 4; nf++) {
            int row = row0 + wm * 64 + mf * 16 + group;
            int col = col0 + wn * 32 + nf * 8 + 2 * tig;
            float2 bv2 = *(const float2*)(bias + col);
            int h = col >> 6, d = col & 63;
            #pragma unroll
            for (int hi = 0; hi < 2; hi++) {
                int r = row + hi * 8;
                int b = r >> 11, l = r & (SEQ - 1);
                __half2 o = __floats2half2_rn(F.c[mf][nf][hi * 2 + 0] + bv2.x,
                                              F.c[mf][nf][hi * 2 + 1] + bv2.y);
                *(__half2*)(C + (((size_t)(b * NHEAD + h) * SEQ) + l) * HEAD_DIM + d) = o;
            }
        }
    }
}

// MODE 1: half out = gelu(acc+bias).  MODE 2: float out = res + acc + bias.
template<int MODE>
__global__ __launch_bounds__(256, 2)
void tc_gemm(const __half* __restrict__ A, const __half* __restrict__ WT,
             const float* __restrict__ bias, const float* __restrict__ res,
             void* __restrict__ Cv, int N, int K)
{
    extern __shared__ __half sm[];
    int row0 = blockIdx.y * BM;
    int col0 = blockIdx.x * BN;
    Frag F;
    mma_mainloop(A, WT, K, row0, col0, sm, F);

    int lane = threadIdx.x & 31, wid = threadIdx.x >> 5;
    int wm = wid >> 2, wn = wid & 3;
    int group = lane >> 2, tig = lane & 3;

    #pragma unroll
    for (int mf = 0; mf < 4; mf++) {
        #pragma unroll
        for (int nf = 0; nf < 4; nf++) {
            int row = row0 + wm * 64 + mf * 16 + group;
            int col = col0 + wn * 32 + nf * 8 + 2 * tig;
            float2 bv2 = *(const float2*)(bias + col);
            #pragma unroll
            for (int hi = 0; hi < 2; hi++) {
                int r = row + hi * 8;
                float ox = F.c[mf][nf][hi * 2 + 0] + bv2.x;
                float oy = F.c[mf][nf][hi * 2 + 1] + bv2.y;
                if (MODE == 1) {
                    __half2 o = __floats2half2_rn(gelu_exact(ox), gelu_exact(oy));
                    *(__half2*)((__half*)Cv + (size_t)r * N + col) = o;
                } else {
                    float2 r2 = *(const float2*)(res + (size_t)r * N + col);
                    float2 o; o.x = ox + r2.x; o.y = oy + r2.y;
                    *(float2*)((float*)Cv + (size_t)r * N + col) = o;
                }
            }
        }
    }
}

// ---------------------------------------------------------------------------
// fp16 mma flash attention (causal). 128 q rows/block, 8 warps, 64-key tiles.
// K fragments via ldmatrix, V fragments via ldmatrix.trans (no Vt staging).
// ---------------------------------------------------------------------------
__global__ __launch_bounds__(256)
void attn_kernel(const __half* __restrict__ Q, const __half* __restrict__ K,
                 const __half* __restrict__ V, __half* __restrict__ out)
{
    __shared__ __half Qs[128][72];
    __shared__ __half Ks[64][72];
    __shared__ __half Vs[64][72];   // natural [key][d]

    int tid = threadIdx.x;
    int lane = tid & 31, wid = tid >> 5;
    int group = lane >> 2, tig = lane & 3;
    int rr = lane & 7, mat = lane >> 3;
    int qb = blockIdx.x * 128;
    int bh = blockIdx.y;
    int wb = wid * 16;

    const __half* Qb = Q + (size_t)bh * SEQ * HEAD_DIM;
    const __half* Kb = K + (size_t)bh * SEQ * HEAD_DIM;
    const __half* Vb = V + (size_t)bh * SEQ * HEAD_DIM;

    #pragma unroll
    for (int i = 0; i < 4; i++) {
        int e = tid + i * 256;
        int r = e >> 3, c = e & 7;
        *(uint4*)&Qs[r][c * 8] = *(const uint4*)(Qb + (size_t)(qb + r) * HEAD_DIM + c * 8);
    }
    __syncthreads();

    uint32_t qa[4][4];
    #pragma unroll
    for (int ks = 0; ks < 4; ks++) {
        int kb = ks * 16 + 2 * tig;
        qa[ks][0] = *(const uint32_t*)&Qs[wb + group][kb];
        qa[ks][1] = *(const uint32_t*)&Qs[wb + group + 8][kb];
        qa[ks][2] = *(const uint32_t*)&Qs[wb + group][kb + 8];
        qa[ks][3] = *(const uint32_t*)&Qs[wb + group + 8][kb + 8];
    }

    // ldmatrix base offsets (per nf-pair p = 0..3)
    // K (non-trans): r0=b0(n=p*16..), r1=b1, r2=b0(n+8), r3=b1(n+8)
    uint32_t offK[4], offV[4];
    #pragma unroll
    for (int p = 0; p < 4; p++) {
        offK[p] = smem_u32(&Ks[p * 16 + rr + ((mat & 2) ? 8 : 0)][(mat & 1) ? 8 : 0]);
        // V (trans): rows = key (k), cols = d; mat0/1 -> b0/b1 of d-group p*16,
        // mat2/3 -> b0/b1 of d-group p*16+8
        offV[p] = smem_u32(&Vs[rr + ((mat & 1) ? 8 : 0)][p * 16 + ((mat & 2) ? 8 : 0)]);
    }

    float o[8][4];
    #pragma unroll
    for (int i = 0; i < 8; i++)
        #pragma unroll
        for (int j = 0; j < 4; j++) o[i][j] = 0.f;
    float m2[2] = {-1e30f, -1e30f};
    float l2[2] = {0.f, 0.f};

    const float scale = 0.125f;
    int row_g0 = qb + wb + group;
    int nkt = (qb >> 6) + 2;

    for (int kt = 0; kt < nkt; kt++) {
        __syncthreads();
        #pragma unroll
        for (int i = 0; i < 2; i++) {
            int e = tid + i * 256;
            int r = e >> 3, c = e & 7;
            *(uint4*)&Ks[r][c * 8] = *(const uint4*)(Kb + (size_t)(kt * 64 + r) * HEAD_DIM + c * 8);
            *(uint4*)&Vs[r][c * 8] = *(const uint4*)(Vb + (size_t)(kt * 64 + r) * HEAD_DIM + c * 8);
        }
        __syncthreads();

        bool active = (kt * 64) <= (qb + wb + 15);
        if (active) {
            float s[8][4];
            #pragma unroll
            for (int nf = 0; nf < 8; nf++)
                #pragma unroll
                for (int c = 0; c < 4; c++) s[nf][c] = 0.f;
            #pragma unroll
            for (int ks = 0; ks < 4; ks++) {
                #pragma unroll
                for (int p = 0; p < 4; p++) {
                    uint32_t kb4[4];
                    LDSM4(kb4, offK[p] + ks * 32);
                    mma_f16(s[2*p],   qa[ks][0], qa[ks][1], qa[ks][2], qa[ks][3], kb4[0], kb4[1]);
                    mma_f16(s[2*p+1], qa[ks][0], qa[ks][1], qa[ks][2], qa[ks][3], kb4[2], kb4[3]);
                }
            }

            bool need_mask = (kt * 64 + 63) > (qb + wb);
            #pragma unroll
            for (int nf = 0; nf < 8; nf++) {
                #pragma unroll
                for (int c = 0; c < 4; c++) {
                    float v = s[nf][c] * scale;
                    if (need_mask) {
                        int key = kt * 64 + nf * 8 + 2 * tig + (c & 1);
                        int rg  = row_g0 + ((c >= 2) ? 8 : 0);
                        if (key > rg) v = -1e30f;
                    }
                    s[nf][c] = v;
                }
            }

            #pragma unroll
            for (int r = 0; r < 2; r++) {
                float mx = -1e30f;
                #pragma unroll
                for (int nf = 0; nf < 8; nf++)
                    mx = fmaxf(mx, fmaxf(s[nf][2 * r], s[nf][2 * r + 1]));
                mx = fmaxf(mx, __shfl_xor_sync(0xffffffffu, mx, 1));
                mx = fmaxf(mx, __shfl_xor_sync(0xffffffffu, mx, 2));
                float mnew = fmaxf(m2[r], mx);
                float corr = __expf(m2[r] - mnew);
                float rsum = 0.f;
                #pragma unroll
                for (int nf = 0; nf < 8; nf++) {
                    float p0 = __expf(s[nf][2 * r]     - mnew);
                    float p1 = __expf(s[nf][2 * r + 1] - mnew);
                    s[nf][2 * r] = p0; s[nf][2 * r + 1] = p1;
                    rsum += p0 + p1;
                }
                rsum += __shfl_xor_sync(0xffffffffu, rsum, 1);
                rsum += __shfl_xor_sync(0xffffffffu, rsum, 2);
                l2[r] = l2[r] * corr + rsum;
                m2[r] = mnew;
                #pragma unroll
                for (int nfd = 0; nfd < 8; nfd++) {
                    o[nfd][2 * r]     *= corr;
                    o[nfd][2 * r + 1] *= corr;
                }
            }

            #pragma unroll
            for (int ks = 0; ks < 4; ks++) {
                uint32_t pa0 = pack_f2h2(s[2*ks][0],   s[2*ks][1]);
                uint32_t pa1 = pack_f2h2(s[2*ks][2],   s[2*ks][3]);
                uint32_t pa2 = pack_f2h2(s[2*ks+1][0], s[2*ks+1][1]);
                uint32_t pa3 = pack_f2h2(s[2*ks+1][2], s[2*ks+1][3]);
                #pragma unroll
                for (int p = 0; p < 4; p++) {
                    uint32_t vb4[4];
                    LDSM4T(vb4, offV[p] + ks * (16 * 72 * 2));
                    mma_f16(o[2*p],   pa0, pa1, pa2, pa3, vb4[0], vb4[1]);
                    mma_f16(o[2*p+1], pa0, pa1, pa2, pa3, vb4[2], vb4[3]);
                }
            }
        }
    }

    int b = bh >> 4, h = bh & 15;
    float inv0 = 1.0f / l2[0];
    float inv1 = 1.0f / l2[1];
    #pragma unroll
    for (int r = 0; r < 2; r++) {
        int rg = row_g0 + r * 8;
        int l = rg & (SEQ - 1);
        float inv = r ? inv1 : inv0;
        #pragma unroll
        for (int nfd = 0; nfd < 8; nfd++) {
            int d = nfd * 8 + 2 * tig;
            __half2 ov = __floats2half2_rn(o[nfd][2 * r] * inv, o[nfd][2 * r + 1] * inv);
            *(__half2*)(out + ((size_t)(b * SEQ + l)) * D_MODEL + h * HEAD_DIM + d) = ov;
        }
    }
}

// ---------------------------------------------------------------------------
// Launch
// ---------------------------------------------------------------------------
extern "C" void kernel_launch(void* const* d_in, const int* in_sizes, int n_in,
                              void* d_out, int out_size)
{
    const float* x   = (const float*)d_in[0];
    const float* Wq  = (const float*)d_in[2];
    const float* bq  = (const float*)d_in[3];
    const float* Wk  = (const float*)d_in[4];
    const float* bk  = (const float*)d_in[5];
    const float* Wv  = (const float*)d_in[6];
    const float* bv  = (const float*)d_in[7];
    const float* Wo  = (const float*)d_in[8];
    const float* bo  = (const float*)d_in[9];
    const float* g1  = (const float*)d_in[10];
    const float* b1  = (const float*)d_in[11];
    const float* g2  = (const float*)d_in[12];
    const float* b2  = (const float*)d_in[13];
    const float* W1  = (const float*)d_in[14];
    const float* bf1 = (const float*)d_in[15];
    const float* W2  = (const float*)d_in[16];
    const float* bf2 = (const float*)d_in[17];
    float* out = (float*)d_out;

    __half *p_nx, *p_q, *p_k, *p_v, *p_attn, *p_nx2, *p_ffh;
    __half *p_wqt, *p_wkt, *p_wvt, *p_wot, *p_w1t, *p_w2t;
    float *p_x1;
    cudaGetSymbolAddress((void**)&p_nx,   g_nx);
    cudaGetSymbolAddress((void**)&p_q,    g_q);
    cudaGetSymbolAddress((void**)&p_k,    g_k);
    cudaGetSymbolAddress((void**)&p_v,    g_v);
    cudaGetSymbolAddress((void**)&p_attn, g_attn);
    cudaGetSymbolAddress((void**)&p_x1,   g_x1);
    cudaGetSymbolAddress((void**)&p_nx2,  g_nx2);
    cudaGetSymbolAddress((void**)&p_ffh,  g_ffh);
    cudaGetSymbolAddress((void**)&p_wqt,  g_wqt);
    cudaGetSymbolAddress((void**)&p_wkt,  g_wkt);
    cudaGetSymbolAddress((void**)&p_wvt,  g_wvt);
    cudaGetSymbolAddress((void**)&p_wot,  g_wot);
    cudaGetSymbolAddress((void**)&p_w1t,  g_w1t);
    cudaGetSymbolAddress((void**)&p_w2t,  g_w2t);

    cudaFuncSetAttribute(tc_gemm_qkv, cudaFuncAttributeMaxDynamicSharedMemorySize, GEMM_SMEM);
    cudaFuncSetAttribute(tc_gemm<1>,  cudaFuncAttributeMaxDynamicSharedMemorySize, GEMM_SMEM);
    cudaFuncSetAttribute(tc_gemm<2>,  cudaFuncAttributeMaxDynamicSharedMemorySize, GEMM_SMEM);

    dim3 t256(256);

    // 0. transpose weights to [N][K] half (QKVO batched; W1, W2 separate)
    transpose4_kernel<<<dim3(D_MODEL/64, D_MODEL/64, 4), t256>>>(
        Wq, Wk, Wv, Wo, p_wqt, p_wkt, p_wvt, p_wot);
    transpose_kernel<<<dim3(D_FF/64,    D_MODEL/64), t256>>>(W1, p_w1t, D_MODEL, D_FF);
    transpose_kernel<<<dim3(D_MODEL/64, D_FF/64),    t256>>>(W2, p_w2t, D_FF,    D_MODEL);

    // 1. nx = LN1(x)
    ln_kernel<<<MROWS, t256>>>(x, g1, b1, p_nx);

    // 2. Q/K/V
    dim3 gQKV(D_MODEL / BN, MROWS / BM, 3);
    tc_gemm_qkv<<<gQKV, t256, GEMM_SMEM>>>(p_nx, p_wqt, p_wkt, p_wvt,
                                           bq, bk, bv, p_q, p_k, p_v);

    // 3. causal flash attention
    dim3 gAttn(SEQ / 128, BATCH * NHEAD);
    attn_kernel<<<gAttn, t256>>>(p_q, p_k, p_v, p_attn);

    // 4. x1 = x + attn @ Wo + bo
    dim3 gD(D_MODEL / BN, MROWS / BM);
    tc_gemm<2><<<gD, t256, GEMM_SMEM>>>(p_attn, p_wot, bo, x, p_x1, D_MODEL, D_MODEL);

    // 5. nx2 = LN2(x1)
    ln_kernel<<<MROWS, t256>>>(p_x1, g2, b2, p_nx2);

    // 6. h = gelu(nx2 @ W1 + bf1)
    dim3 gF1(D_FF / BN, MROWS / BM);
    tc_gemm<1><<<gF1, t256, GEMM_SMEM>>>(p_nx2, p_w1t, bf1, nullptr, p_ffh, D_FF, D_MODEL);

    // 7. out = x1 + h @ W2 + bf2
    tc_gemm<2><<<gD, t256, GEMM_SMEM>>>(p_ffh, p_w2t, bf2, p_x1, out, D_MODEL, D_FF);
}